// round 1
// baseline (speedup 1.0000x reference)
#include <cuda_runtime.h>
#include <math.h>

// Problem constants
#define BATCH 4
#define SEQ   2048
#define EMB   1024
#define HEADS 16
#define DHEAD 64
#define MTOT  (BATCH*SEQ)      // 8192
#define FFN   (4*EMB)          // 4096

// ---------------- scratch (no allocs allowed) ----------------
__device__ float g_lnx[(size_t)MTOT*EMB];   // LN1 out, reused for LN2 out
__device__ float g_q  [(size_t)MTOT*EMB];
__device__ float g_k  [(size_t)MTOT*EMB];
__device__ float g_v  [(size_t)MTOT*EMB];
__device__ float g_ctx[(size_t)MTOT*EMB];
__device__ float g_h  [(size_t)MTOT*EMB];
__device__ float g_mid[(size_t)MTOT*FFN];

// ---------------- utilities ----------------
__device__ __forceinline__ float warp_sum(float v) {
    #pragma unroll
    for (int o = 16; o > 0; o >>= 1) v += __shfl_xor_sync(0xffffffffu, v, o);
    return v;
}
__device__ __forceinline__ float warp_max(float v) {
    #pragma unroll
    for (int o = 16; o > 0; o >>= 1) v = fmaxf(v, __shfl_xor_sync(0xffffffffu, v, o));
    return v;
}

// ---------------- LayerNorm: one row per block ----------------
__global__ void layernorm_kernel(const float* __restrict__ x,
                                 const float* __restrict__ gamma,
                                 const float* __restrict__ beta,
                                 float* __restrict__ out) {
    const int row = blockIdx.x;
    const float* xr = x + (size_t)row * EMB;
    float s = 0.f, s2 = 0.f;
    for (int i = threadIdx.x; i < EMB; i += blockDim.x) {
        float v = xr[i];
        s += v; s2 += v * v;
    }
    s = warp_sum(s); s2 = warp_sum(s2);
    __shared__ float sh[2][8];
    int lane = threadIdx.x & 31, wid = threadIdx.x >> 5;
    if (lane == 0) { sh[0][wid] = s; sh[1][wid] = s2; }
    __syncthreads();
    if (wid == 0) {
        float a = (lane < 8) ? sh[0][lane] : 0.f;
        float b = (lane < 8) ? sh[1][lane] : 0.f;
        a = warp_sum(a); b = warp_sum(b);
        if (lane == 0) { sh[0][0] = a; sh[1][0] = b; }
    }
    __syncthreads();
    float mean = sh[0][0] * (1.0f / EMB);
    float var  = sh[1][0] * (1.0f / EMB) - mean * mean;
    float inv  = rsqrtf(var + 1e-5f);
    float* outr = out + (size_t)row * EMB;
    for (int i = threadIdx.x; i < EMB; i += blockDim.x) {
        outr[i] = gamma[i] * ((xr[i] - mean) * inv) + beta[i];
    }
}

// ---------------- SGEMM 128x128x16, 256 threads, 8x8 microtile ----------------
// C[M,N] = A[M,K] @ B[K,N]  (+bias[n]) (GELU?) (+residual[m,n])
template<bool DO_GELU>
__global__ void __launch_bounds__(256, 2)
sgemm_kernel(const float* __restrict__ A, const float* __restrict__ B,
             float* __restrict__ C, int M, int N, int K,
             const float* __restrict__ bias,
             const float* __restrict__ residual) {
    const int BM = 128, BN = 128, BK = 16;
    __shared__ float As[BK][BM];
    __shared__ float Bs[BK][BN];

    const int bm = blockIdx.y * BM;
    const int bn = blockIdx.x * BN;
    const int tid = threadIdx.x;
    const int tx = tid & 15;        // 0..15
    const int ty = tid >> 4;        // 0..15

    // load mappings
    const int a_row = tid >> 2;            // 0..63
    const int a_col = (tid & 3) * 4;       // 0,4,8,12
    const int b_row = tid >> 5;            // 0..7
    const int b_col = (tid & 31) * 4;      // 0..124

    float acc[8][8];
    #pragma unroll
    for (int i = 0; i < 8; i++)
        #pragma unroll
        for (int j = 0; j < 8; j++) acc[i][j] = 0.f;

    for (int k0 = 0; k0 < K; k0 += BK) {
        #pragma unroll
        for (int p = 0; p < 2; p++) {
            int r = a_row + p * 64;
            float4 v = *(const float4*)(A + (size_t)(bm + r) * K + k0 + a_col);
            As[a_col + 0][r] = v.x;
            As[a_col + 1][r] = v.y;
            As[a_col + 2][r] = v.z;
            As[a_col + 3][r] = v.w;
        }
        #pragma unroll
        for (int p = 0; p < 2; p++) {
            int r = b_row + p * 8;
            float4 v = *(const float4*)(B + (size_t)(k0 + r) * N + bn + b_col);
            *(float4*)&Bs[r][b_col] = v;
        }
        __syncthreads();

        #pragma unroll
        for (int k = 0; k < BK; k++) {
            float a[8], b[8];
            float4 a0 = *(const float4*)&As[k][ty * 4];
            float4 a1 = *(const float4*)&As[k][64 + ty * 4];
            a[0]=a0.x; a[1]=a0.y; a[2]=a0.z; a[3]=a0.w;
            a[4]=a1.x; a[5]=a1.y; a[6]=a1.z; a[7]=a1.w;
            float4 b0 = *(const float4*)&Bs[k][tx * 4];
            float4 b1 = *(const float4*)&Bs[k][64 + tx * 4];
            b[0]=b0.x; b[1]=b0.y; b[2]=b0.z; b[3]=b0.w;
            b[4]=b1.x; b[5]=b1.y; b[6]=b1.z; b[7]=b1.w;
            #pragma unroll
            for (int i = 0; i < 8; i++)
                #pragma unroll
                for (int j = 0; j < 8; j++)
                    acc[i][j] += a[i] * b[j];
        }
        __syncthreads();
    }

    // epilogue
    #pragma unroll
    for (int i = 0; i < 8; i++) {
        int m = bm + ((i < 4) ? (ty * 4 + i) : (64 + ty * 4 + (i - 4)));
        #pragma unroll
        for (int j = 0; j < 8; j++) {
            int n = bn + ((j < 4) ? (tx * 4 + j) : (64 + tx * 4 + (j - 4)));
            float v = acc[i][j];
            if (bias) v += bias[n];
            if (DO_GELU) v = 0.5f * v * (1.0f + erff(v * 0.70710678118654752f));
            if (residual) v += residual[(size_t)m * N + n];
            C[(size_t)m * N + n] = v;
        }
    }
}

// ---------------- Flash attention (causal), 1 warp = 1 query row ----------------
// q,k,v,ctx: [B*S, H*DH] row-major. grid: (S/8, B*H), 256 threads (8 warps).
__global__ void __launch_bounds__(256, 2)
attention_kernel(const float* __restrict__ Q, const float* __restrict__ K,
                 const float* __restrict__ V, float* __restrict__ ctx) {
    __shared__ float K_sh[64][65];
    __shared__ float V_sh[64][65];
    __shared__ float Q_sh[8][64];
    __shared__ float P_sh[8][64];

    const int tid  = threadIdx.x;
    const int w    = tid >> 5;     // warp 0..7
    const int lane = tid & 31;
    const int bh   = blockIdx.y;
    const int b    = bh >> 4;      // /HEADS
    const int h    = bh & 15;
    const int base = b * SEQ;      // row base of this batch
    const int hcol = h * DHEAD;

    const int s = blockIdx.x * 8 + w;          // query position (0..2047)
    const int s_max = blockIdx.x * 8 + 7;      // max q pos in block
    const size_t qoff = (size_t)(base + s) * EMB + hcol;

    // load my q row
    Q_sh[w][lane]      = Q[qoff + lane];
    Q_sh[w][lane + 32] = Q[qoff + lane + 32];
    __syncwarp();

    float m = -INFINITY, ssum = 0.f, o0 = 0.f, o1 = 0.f;

    for (int k0 = 0; k0 <= s_max; k0 += 64) {
        // cooperative K/V tile load
        for (int i = tid; i < 64 * 64; i += 256) {
            int r = i >> 6, c = i & 63;
            size_t goff = (size_t)(base + k0 + r) * EMB + hcol + c;
            K_sh[r][c] = K[goff];
            V_sh[r][c] = V[goff];
        }
        __syncthreads();

        if (k0 <= s) {
            // scores for k = k0+lane and k0+lane+32
            float accA = 0.f, accB = 0.f;
            #pragma unroll
            for (int d = 0; d < 64; d++) {
                float qd = Q_sh[w][d];
                accA += qd * K_sh[lane][d];
                accB += qd * K_sh[lane + 32][d];
            }
            float sa = (k0 + lane      <= s) ? accA * 0.125f : -INFINITY;
            float sb = (k0 + lane + 32 <= s) ? accB * 0.125f : -INFINITY;

            float tmax = warp_max(fmaxf(sa, sb));
            float newm = fmaxf(m, tmax);
            float corr = __expf(m - newm);
            float pa = __expf(sa - newm);
            float pb = __expf(sb - newm);
            ssum = ssum * corr + warp_sum(pa + pb);

            P_sh[w][lane]      = pa;
            P_sh[w][lane + 32] = pb;
            __syncwarp();

            float acc0 = 0.f, acc1 = 0.f;
            #pragma unroll
            for (int kk = 0; kk < 64; kk++) {
                float p = P_sh[w][kk];
                acc0 += p * V_sh[kk][lane];
                acc1 += p * V_sh[kk][lane + 32];
            }
            o0 = o0 * corr + acc0;
            o1 = o1 * corr + acc1;
            m = newm;
            __syncwarp();
        }
        __syncthreads();
    }

    float inv = 1.0f / ssum;
    ctx[qoff + lane]      = o0 * inv;
    ctx[qoff + lane + 32] = o1 * inv;
}

// ---------------- launch ----------------
extern "C" void kernel_launch(void* const* d_in, const int* in_sizes, int n_in,
                              void* d_out, int out_size) {
    const float* x     = (const float*)d_in[0];
    const float* Wq    = (const float*)d_in[1];
    const float* Wk    = (const float*)d_in[2];
    const float* Wv    = (const float*)d_in[3];
    const float* Wo    = (const float*)d_in[4];
    const float* bo    = (const float*)d_in[5];
    const float* W1    = (const float*)d_in[6];
    const float* b1    = (const float*)d_in[7];
    const float* W2    = (const float*)d_in[8];
    const float* b2    = (const float*)d_in[9];
    const float* g1    = (const float*)d_in[10];
    const float* beta1 = (const float*)d_in[11];
    const float* g2    = (const float*)d_in[12];
    const float* beta2 = (const float*)d_in[13];
    float* out = (float*)d_out;

    float *lnx, *q, *k, *v, *ctx, *h, *mid;
    cudaGetSymbolAddress((void**)&lnx, g_lnx);
    cudaGetSymbolAddress((void**)&q,   g_q);
    cudaGetSymbolAddress((void**)&k,   g_k);
    cudaGetSymbolAddress((void**)&v,   g_v);
    cudaGetSymbolAddress((void**)&ctx, g_ctx);
    cudaGetSymbolAddress((void**)&h,   g_h);
    cudaGetSymbolAddress((void**)&mid, g_mid);

    dim3 gEE(EMB / 128, MTOT / 128);   // (8, 64)
    dim3 gEF(FFN / 128, MTOT / 128);   // (32, 64)

    // 1) LN1
    layernorm_kernel<<<MTOT, 256>>>(x, g1, beta1, lnx);
    // 2) QKV projections
    sgemm_kernel<false><<<gEE, 256>>>(lnx, Wq, q, MTOT, EMB, EMB, nullptr, nullptr);
    sgemm_kernel<false><<<gEE, 256>>>(lnx, Wk, k, MTOT, EMB, EMB, nullptr, nullptr);
    sgemm_kernel<false><<<gEE, 256>>>(lnx, Wv, v, MTOT, EMB, EMB, nullptr, nullptr);
    // 3) causal attention
    attention_kernel<<<dim3(SEQ / 8, BATCH * HEADS), 256>>>(q, k, v, ctx);
    // 4) output proj + bias + residual -> h
    sgemm_kernel<false><<<gEE, 256>>>(ctx, Wo, h, MTOT, EMB, EMB, bo, x);
    // 5) LN2
    layernorm_kernel<<<MTOT, 256>>>(h, g2, beta2, lnx);
    // 6) FFN up + bias + GELU
    sgemm_kernel<true><<<gEF, 256>>>(lnx, W1, mid, MTOT, FFN, EMB, b1, nullptr);
    // 7) FFN down + bias + residual -> out
    sgemm_kernel<false><<<gEE, 256>>>(mid, W2, out, MTOT, EMB, FFN, b2, h);
}

// round 3
// speedup vs baseline: 1.8628x; 1.8628x over previous
#include <cuda_runtime.h>
#include <math.h>
#include <stdint.h>

// Problem constants
#define BATCH 4
#define SEQ   2048
#define EMB   1024
#define HEADS 16
#define DHEAD 64
#define MTOT  (BATCH*SEQ)      // 8192
#define FFN   (4*EMB)          // 4096

// tcgen05 is arch-specific: only emit it in the sm_103a device pass.
// The compute_103 (portable PTX) pass gets an empty body that never runs on GB300.
#if defined(__CUDA_ARCH__) && (defined(__CUDA_ARCH_FEAT_SM103_ALL) || defined(__CUDA_ARCH_FEAT_SM100_ALL))
#define TC_OK 1
#else
#define TC_OK 0
#endif

// ---------------- scratch (no allocs allowed) ----------------
__device__ float g_lnx[(size_t)MTOT*EMB];
__device__ float g_q  [(size_t)MTOT*EMB];
__device__ float g_k  [(size_t)MTOT*EMB];
__device__ float g_v  [(size_t)MTOT*EMB];
__device__ float g_ctx[(size_t)MTOT*EMB];
__device__ float g_h  [(size_t)MTOT*EMB];
__device__ float g_mid[(size_t)MTOT*FFN];

// ---------------- helpers ----------------
__device__ __forceinline__ uint32_t smem_u32(const void* p) {
    uint32_t a;
    asm("{ .reg .u64 t; cvta.to.shared.u64 t, %1; cvt.u32.u64 %0, t; }" : "=r"(a) : "l"(p));
    return a;
}
__device__ __forceinline__ uint32_t f2tf32(float f) {
    uint32_t r;
    asm("cvt.rna.tf32.f32 %0, %1;" : "=r"(r) : "f"(f));
    return r;
}
#define SWZ(o) ((o) ^ (((o) >> 3) & 0x70))

#define MBAR_INIT(a, c) asm volatile("mbarrier.init.shared.b64 [%0], %1;" :: "r"(a), "r"(c) : "memory")
#define MBAR_INVAL(a)   asm volatile("mbarrier.inval.shared.b64 [%0];" :: "r"(a) : "memory")
#define MBAR_WAIT(a, ph) do { \
    uint32_t _m = (a); uint32_t _p = (ph); uint32_t _d; \
    asm volatile("{ .reg .pred p; mbarrier.try_wait.parity.acquire.cta.shared::cta.b64 p, [%1], %2; selp.b32 %0,1,0,p; }" \
        : "=r"(_d) : "r"(_m), "r"(_p) : "memory"); \
    if (!_d) { \
        asm volatile("{ .reg .pred P1; WL_%=: mbarrier.try_wait.parity.acquire.cta.shared::cta.b64 P1, [%0], %1, 0x989680; @P1 bra.uni WD_%=; bra.uni WL_%=; WD_%=: }" \
            :: "r"(_m), "r"(_p) : "memory"); \
    } } while (0)

#if TC_OK
__device__ __forceinline__ uint32_t elect1() {
    uint32_t p;
    asm volatile("{ .reg .pred p; elect.sync _|p, 0xFFFFFFFF; selp.b32 %0,1,0,p; }" : "=r"(p));
    return p;
}
__device__ __forceinline__ uint64_t make_desc_sw128(uint32_t addr) {
    const uint64_t base = (2ull << 61) | (1ull << 46) | (64ull << 32) | (1ull << 16);
    return base | ((uint64_t)(addr >> 4) & 0x3FFF);
}
#define LDTM_X32(r, addr) \
    asm volatile("tcgen05.ld.sync.aligned.32x32b.x32.b32 " \
        "{%0,%1,%2,%3,%4,%5,%6,%7,%8,%9,%10,%11,%12,%13,%14,%15," \
        "%16,%17,%18,%19,%20,%21,%22,%23,%24,%25,%26,%27,%28,%29,%30,%31}, [%32];" \
        : "=r"((r)[0]),"=r"((r)[1]),"=r"((r)[2]),"=r"((r)[3]),"=r"((r)[4]),"=r"((r)[5]),"=r"((r)[6]),"=r"((r)[7]), \
          "=r"((r)[8]),"=r"((r)[9]),"=r"((r)[10]),"=r"((r)[11]),"=r"((r)[12]),"=r"((r)[13]),"=r"((r)[14]),"=r"((r)[15]), \
          "=r"((r)[16]),"=r"((r)[17]),"=r"((r)[18]),"=r"((r)[19]),"=r"((r)[20]),"=r"((r)[21]),"=r"((r)[22]),"=r"((r)[23]), \
          "=r"((r)[24]),"=r"((r)[25]),"=r"((r)[26]),"=r"((r)[27]),"=r"((r)[28]),"=r"((r)[29]),"=r"((r)[30]),"=r"((r)[31]) \
        : "r"(addr))

__device__ __forceinline__ void mma_tf32_ss(uint32_t d, uint64_t ad, uint64_t bd,
                                            uint32_t idesc, uint32_t en) {
    asm volatile("{\n\t.reg .pred p;\n\tsetp.ne.u32 p, %5, 0;\n\t"
        "tcgen05.mma.cta_group::1.kind::tf32 [%0], %1, %2, %3, {%4,%4,%4,%4}, p;\n\t}"
        :: "r"(d), "l"(ad), "l"(bd), "r"(idesc), "r"(0u), "r"(en) : "memory");
}
#endif

// ---------------- LayerNorm ----------------
__device__ __forceinline__ float warp_sum(float v) {
    #pragma unroll
    for (int o = 16; o > 0; o >>= 1) v += __shfl_xor_sync(0xffffffffu, v, o);
    return v;
}
__device__ __forceinline__ float warp_max(float v) {
    #pragma unroll
    for (int o = 16; o > 0; o >>= 1) v = fmaxf(v, __shfl_xor_sync(0xffffffffu, v, o));
    return v;
}

__global__ void layernorm_kernel(const float* __restrict__ x,
                                 const float* __restrict__ gamma,
                                 const float* __restrict__ beta,
                                 float* __restrict__ out) {
    const int row = blockIdx.x;
    const float* xr = x + (size_t)row * EMB;
    float s = 0.f, s2 = 0.f;
    for (int i = threadIdx.x; i < EMB; i += blockDim.x) {
        float v = xr[i];
        s += v; s2 += v * v;
    }
    s = warp_sum(s); s2 = warp_sum(s2);
    __shared__ float sh[2][8];
    int lane = threadIdx.x & 31, wid = threadIdx.x >> 5;
    if (lane == 0) { sh[0][wid] = s; sh[1][wid] = s2; }
    __syncthreads();
    if (wid == 0) {
        float a = (lane < 8) ? sh[0][lane] : 0.f;
        float b = (lane < 8) ? sh[1][lane] : 0.f;
        a = warp_sum(a); b = warp_sum(b);
        if (lane == 0) { sh[0][0] = a; sh[1][0] = b; }
    }
    __syncthreads();
    float mean = sh[0][0] * (1.0f / EMB);
    float var  = sh[1][0] * (1.0f / EMB) - mean * mean;
    float inv  = rsqrtf(var + 1e-5f);
    float* outr = out + (size_t)row * EMB;
    for (int i = threadIdx.x; i < EMB; i += blockDim.x) {
        outr[i] = gamma[i] * ((xr[i] - mean) * inv) + beta[i];
    }
}

// ---------------- tcgen05 tf32 GEMM: 128x256 tile, BK=32, double-buffered ----------------
#define BM 128
#define BN 256
#define BK 32
#define ABYTES (BM*128)            // 16384
#define BBYTES (BN*128)            // 32768
#define BUFBYTES (ABYTES+BBYTES)   // 49152
#define SMEM_DYN (2*BUFBYTES + 1024)  // +1KB alignment slack

#define IDESC_TF32 ((1u << 4) | (2u << 7) | (2u << 10) | ((BN / 8) << 17) | ((BM / 16) << 24))

template<bool GELU, bool BIAS, bool RES>
__global__ void __launch_bounds__(256, 2)
tc_gemm(const float* __restrict__ A, const float* __restrict__ B,
        float* __restrict__ C, int M, int N, int K,
        const float* __restrict__ bias, const float* __restrict__ res) {
#if TC_OK
    extern __shared__ char sm_raw[];
    __shared__ uint32_t s_tmem;
    __shared__ __align__(8) uint64_t s_mbar[2];

    const int tid = threadIdx.x, wid = tid >> 5, lane = tid & 31;
    const int bm = blockIdx.y * BM, bn = blockIdx.x * BN;

    uint32_t smb_raw = smem_u32(sm_raw);
    uint32_t smb = (smb_raw + 1023u) & ~1023u;
    char* sm = sm_raw + (smb - smb_raw);
    uint32_t mbar0 = smem_u32(&s_mbar[0]);

    if (wid == 4) {
        asm volatile("tcgen05.alloc.cta_group::1.sync.aligned.shared::cta.b32 [%0], %1;"
                     :: "r"(smem_u32(&s_tmem)), "r"(256) : "memory");
    }
    if (tid == 0) { MBAR_INIT(mbar0, 1); MBAR_INIT(mbar0 + 8, 1); }
    __syncthreads();
    const uint32_t tmem = s_tmem;

    const int KIT = K / BK;
    for (int i = 0; i < KIT; i++) {
        const int buf = i & 1;
        const uint32_t abase = (uint32_t)buf * BUFBYTES;
        const uint32_t bbase = abase + ABYTES;
        if (i >= 2) MBAR_WAIT(mbar0 + 8 * buf, ((i - 2) >> 1) & 1);

        const int k0 = i * BK;
        // A tile: [BM rows x 32 tf32] K-major SW128
        #pragma unroll
        for (int p = 0; p < 4; p++) {
            int idx = tid + p * 256;
            int m = idx >> 3, kq = idx & 7;
            float4 v = *(const float4*)(A + (size_t)(bm + m) * K + (k0 + kq * 4));
            uint4 t;
            t.x = f2tf32(v.x); t.y = f2tf32(v.y); t.z = f2tf32(v.z); t.w = f2tf32(v.w);
            *(uint4*)(sm + abase + SWZ((uint32_t)(m * 128 + kq * 16))) = t;
        }
        // B tile: transpose to [BN rows x 32 tf32] K-major SW128
        #pragma unroll
        for (int p = 0; p < 8; p++) {
            int idx = tid + p * 256;
            int n = idx & 255, kq = idx >> 8;
            const float* bp = B + (size_t)(k0 + kq * 4) * N + bn + n;
            uint4 t;
            t.x = f2tf32(bp[0]);
            t.y = f2tf32(bp[(size_t)N]);
            t.z = f2tf32(bp[2 * (size_t)N]);
            t.w = f2tf32(bp[3 * (size_t)N]);
            *(uint4*)(sm + bbase + SWZ((uint32_t)(n * 128 + kq * 16))) = t;
        }
        asm volatile("fence.proxy.async.shared::cta;" ::: "memory");
        __syncthreads();

        if (wid == 4) {
            uint64_t ad = make_desc_sw128(smb + abase);
            uint64_t bd = make_desc_sw128(smb + bbase);
            if (elect1()) {
                #pragma unroll
                for (int kk = 0; kk < 4; kk++) {
                    uint32_t en = (i > 0 || kk > 0) ? 1u : 0u;
                    mma_tf32_ss(tmem, ad + kk * 2, bd + kk * 2, IDESC_TF32, en);
                }
                asm volatile("tcgen05.commit.cta_group::1.mbarrier::arrive::one.shared::cluster.b64 [%0];"
                             :: "r"(mbar0 + 8 * buf) : "memory");
            }
        }
    }

    MBAR_WAIT(mbar0 + 8 * ((KIT - 1) & 1), ((KIT - 1) >> 1) & 1);
    asm volatile("tcgen05.fence::after_thread_sync;" ::: "memory");
    __syncthreads();

    // epilogue: two 128-column halves, staged via padded SMEM
    #pragma unroll
    for (int h = 0; h < 2; h++) {
        if (wid < 4) {
            #pragma unroll
            for (int c = 0; c < 4; c++) {
                uint32_t r[32];
                LDTM_X32(r, tmem + h * 128 + c * 32);
                asm volatile("tcgen05.wait::ld.sync.aligned;" ::: "memory");
                char* row = sm + (wid * 32 + lane) * 528 + c * 128;
                #pragma unroll
                for (int j = 0; j < 8; j++) {
                    float4 v;
                    v.x = __uint_as_float(r[4 * j + 0]);
                    v.y = __uint_as_float(r[4 * j + 1]);
                    v.z = __uint_as_float(r[4 * j + 2]);
                    v.w = __uint_as_float(r[4 * j + 3]);
                    *(float4*)(row + j * 16) = v;
                }
            }
        }
        __syncthreads();
        #pragma unroll
        for (int p = 0; p < 16; p++) {
            int idx = tid + p * 256;
            int r = idx >> 5, cq = idx & 31;
            float4 v = *(float4*)(sm + r * 528 + cq * 16);
            int n = bn + h * 128 + cq * 4;
            size_t off = (size_t)(bm + r) * N + n;
            if (BIAS) {
                float4 bb = *(const float4*)(bias + n);
                v.x += bb.x; v.y += bb.y; v.z += bb.z; v.w += bb.w;
            }
            if (GELU) {
                v.x = 0.5f * v.x * (1.0f + erff(v.x * 0.7071067811865476f));
                v.y = 0.5f * v.y * (1.0f + erff(v.y * 0.7071067811865476f));
                v.z = 0.5f * v.z * (1.0f + erff(v.z * 0.7071067811865476f));
                v.w = 0.5f * v.w * (1.0f + erff(v.w * 0.7071067811865476f));
            }
            if (RES) {
                float4 rr = *(const float4*)(res + off);
                v.x += rr.x; v.y += rr.y; v.z += rr.z; v.w += rr.w;
            }
            *(float4*)(C + off) = v;
        }
        __syncthreads();
    }

    if (tid == 0) { MBAR_INVAL(mbar0); MBAR_INVAL(mbar0 + 8); }
    if (wid == 4) {
        asm volatile("tcgen05.dealloc.cta_group::1.sync.aligned.b32 %0, %1;" :: "r"(tmem), "r"(256));
    }
#endif  // TC_OK
}

// ---------------- Flash attention (causal), 1 warp = 1 query, 16 q/block ----------------
__global__ void __launch_bounds__(512, 2)
attention_kernel(const float* __restrict__ Q, const float* __restrict__ K,
                 const float* __restrict__ V, float* __restrict__ ctx) {
    __shared__ float K_sh[64][65];
    __shared__ float V_sh[64][65];
    __shared__ float Q_sh[16][64];
    __shared__ float P_sh[16][64];

    const int tid  = threadIdx.x;
    const int w    = tid >> 5;     // 0..15
    const int lane = tid & 31;
    const int bh   = blockIdx.y;
    const int b    = bh >> 4;
    const int h    = bh & 15;
    const int base = b * SEQ;
    const int hcol = h * DHEAD;

    const int s = blockIdx.x * 16 + w;
    const int s_max = blockIdx.x * 16 + 15;
    const size_t qoff = (size_t)(base + s) * EMB + hcol;

    Q_sh[w][lane]      = Q[qoff + lane];
    Q_sh[w][lane + 32] = Q[qoff + lane + 32];
    __syncwarp();

    float m = -INFINITY, ssum = 0.f, o0 = 0.f, o1 = 0.f;

    for (int k0 = 0; k0 <= s_max; k0 += 64) {
        for (int i = tid; i < 64 * 64; i += 512) {
            int r = i >> 6, c = i & 63;
            size_t goff = (size_t)(base + k0 + r) * EMB + hcol + c;
            K_sh[r][c] = K[goff];
            V_sh[r][c] = V[goff];
        }
        __syncthreads();

        if (k0 <= s) {
            float accA = 0.f, accB = 0.f;
            #pragma unroll
            for (int d = 0; d < 64; d++) {
                float qd = Q_sh[w][d];
                accA += qd * K_sh[lane][d];
                accB += qd * K_sh[lane + 32][d];
            }
            float sa = (k0 + lane      <= s) ? accA * 0.125f : -INFINITY;
            float sb = (k0 + lane + 32 <= s) ? accB * 0.125f : -INFINITY;

            float tmax = warp_max(fmaxf(sa, sb));
            float newm = fmaxf(m, tmax);
            float corr = __expf(m - newm);
            float pa = __expf(sa - newm);
            float pb = __expf(sb - newm);
            ssum = ssum * corr + warp_sum(pa + pb);

            P_sh[w][lane]      = pa;
            P_sh[w][lane + 32] = pb;
            __syncwarp();

            float acc0 = 0.f, acc1 = 0.f;
            #pragma unroll
            for (int kk = 0; kk < 64; kk++) {
                float p = P_sh[w][kk];
                acc0 += p * V_sh[kk][lane];
                acc1 += p * V_sh[kk][lane + 32];
            }
            o0 = o0 * corr + acc0;
            o1 = o1 * corr + acc1;
            m = newm;
            __syncwarp();
        }
        __syncthreads();
    }

    float inv = 1.0f / ssum;
    ctx[qoff + lane]      = o0 * inv;
    ctx[qoff + lane + 32] = o1 * inv;
}

// ---------------- launch ----------------
extern "C" void kernel_launch(void* const* d_in, const int* in_sizes, int n_in,
                              void* d_out, int out_size) {
    const float* x     = (const float*)d_in[0];
    const float* Wq    = (const float*)d_in[1];
    const float* Wk    = (const float*)d_in[2];
    const float* Wv    = (const float*)d_in[3];
    const float* Wo    = (const float*)d_in[4];
    const float* bo    = (const float*)d_in[5];
    const float* W1    = (const float*)d_in[6];
    const float* b1    = (const float*)d_in[7];
    const float* W2    = (const float*)d_in[8];
    const float* b2    = (const float*)d_in[9];
    const float* g1    = (const float*)d_in[10];
    const float* beta1 = (const float*)d_in[11];
    const float* g2    = (const float*)d_in[12];
    const float* beta2 = (const float*)d_in[13];
    float* out = (float*)d_out;

    float *lnx, *q, *k, *v, *ctx, *h, *mid;
    cudaGetSymbolAddress((void**)&lnx, g_lnx);
    cudaGetSymbolAddress((void**)&q,   g_q);
    cudaGetSymbolAddress((void**)&k,   g_k);
    cudaGetSymbolAddress((void**)&v,   g_v);
    cudaGetSymbolAddress((void**)&ctx, g_ctx);
    cudaGetSymbolAddress((void**)&h,   g_h);
    cudaGetSymbolAddress((void**)&mid, g_mid);

    cudaFuncSetAttribute(tc_gemm<false,false,false>, cudaFuncAttributeMaxDynamicSharedMemorySize, SMEM_DYN);
    cudaFuncSetAttribute(tc_gemm<false,true, true >, cudaFuncAttributeMaxDynamicSharedMemorySize, SMEM_DYN);
    cudaFuncSetAttribute(tc_gemm<true, true, false>, cudaFuncAttributeMaxDynamicSharedMemorySize, SMEM_DYN);

    dim3 gEE(EMB / BN, MTOT / BM);    // (4, 64)
    dim3 gEF(FFN / BN, MTOT / BM);    // (16, 64)

    layernorm_kernel<<<MTOT, 256>>>(x, g1, beta1, lnx);
    tc_gemm<false,false,false><<<gEE, 256, SMEM_DYN>>>(lnx, Wq, q, MTOT, EMB, EMB, nullptr, nullptr);
    tc_gemm<false,false,false><<<gEE, 256, SMEM_DYN>>>(lnx, Wk, k, MTOT, EMB, EMB, nullptr, nullptr);
    tc_gemm<false,false,false><<<gEE, 256, SMEM_DYN>>>(lnx, Wv, v, MTOT, EMB, EMB, nullptr, nullptr);
    attention_kernel<<<dim3(SEQ / 16, BATCH * HEADS), 512>>>(q, k, v, ctx);
    tc_gemm<false,true,true><<<gEE, 256, SMEM_DYN>>>(ctx, Wo, h, MTOT, EMB, EMB, bo, x);
    layernorm_kernel<<<MTOT, 256>>>(h, g2, beta2, lnx);
    tc_gemm<true,true,false><<<gEF, 256, SMEM_DYN>>>(lnx, W1, mid, MTOT, FFN, EMB, b1, nullptr);
    tc_gemm<false,true,true><<<gEE, 256, SMEM_DYN>>>(mid, W2, out, MTOT, EMB, FFN, b2, h);
}

// round 4
// speedup vs baseline: 4.9975x; 2.6827x over previous
#include <cuda_runtime.h>
#include <math.h>
#include <stdint.h>

// Problem constants
#define BATCH 4
#define SEQ   2048
#define EMB   1024
#define HEADS 16
#define DHEAD 64
#define MTOT  (BATCH*SEQ)      // 8192
#define FFN   (4*EMB)          // 4096

// tcgen05 is arch-specific: only emit it in the sm_103a device pass.
#if defined(__CUDA_ARCH__) && (defined(__CUDA_ARCH_FEAT_SM103_ALL) || defined(__CUDA_ARCH_FEAT_SM100_ALL))
#define TC_OK 1
#else
#define TC_OK 0
#endif

// ---------------- scratch (no allocs allowed) ----------------
__device__ float g_lnx[(size_t)MTOT*EMB];
__device__ float g_q  [(size_t)MTOT*EMB];
__device__ float g_k  [(size_t)MTOT*EMB];
__device__ float g_v  [(size_t)MTOT*EMB];
__device__ float g_ctx[(size_t)MTOT*EMB];
__device__ float g_h  [(size_t)MTOT*EMB];
__device__ float g_mid[(size_t)MTOT*FFN];

// ---------------- helpers ----------------
__device__ __forceinline__ uint32_t smem_u32(const void* p) {
    uint32_t a;
    asm("{ .reg .u64 t; cvta.to.shared.u64 t, %1; cvt.u32.u64 %0, t; }" : "=r"(a) : "l"(p));
    return a;
}
__device__ __forceinline__ uint32_t f2tf32(float f) {
    uint32_t r;
    asm("cvt.rna.tf32.f32 %0, %1;" : "=r"(r) : "f"(f));
    return r;
}
#define SWZ(o) ((o) ^ (((o) >> 3) & 0x70))

#define MBAR_INIT(a, c) asm volatile("mbarrier.init.shared.b64 [%0], %1;" :: "r"(a), "r"(c) : "memory")
#define MBAR_INVAL(a)   asm volatile("mbarrier.inval.shared.b64 [%0];" :: "r"(a) : "memory")
#define MBAR_WAIT(a, ph) do { \
    uint32_t _m = (a); uint32_t _p = (ph); uint32_t _d; \
    asm volatile("{ .reg .pred p; mbarrier.try_wait.parity.acquire.cta.shared::cta.b64 p, [%1], %2; selp.b32 %0,1,0,p; }" \
        : "=r"(_d) : "r"(_m), "r"(_p) : "memory"); \
    if (!_d) { \
        asm volatile("{ .reg .pred P1; WL_%=: mbarrier.try_wait.parity.acquire.cta.shared::cta.b64 P1, [%0], %1, 0x989680; @P1 bra.uni WD_%=; bra.uni WL_%=; WD_%=: }" \
            :: "r"(_m), "r"(_p) : "memory"); \
    } } while (0)

#if TC_OK
__device__ __forceinline__ uint32_t elect1() {
    uint32_t p;
    asm volatile("{ .reg .pred p; elect.sync _|p, 0xFFFFFFFF; selp.b32 %0,1,0,p; }" : "=r"(p));
    return p;
}
__device__ __forceinline__ uint64_t make_desc_sw128(uint32_t addr) {
    const uint64_t base = (2ull << 61) | (1ull << 46) | (64ull << 32) | (1ull << 16);
    return base | ((uint64_t)(addr >> 4) & 0x3FFF);
}
#define LDTM_X32(r, addr) \
    asm volatile("tcgen05.ld.sync.aligned.32x32b.x32.b32 " \
        "{%0,%1,%2,%3,%4,%5,%6,%7,%8,%9,%10,%11,%12,%13,%14,%15," \
        "%16,%17,%18,%19,%20,%21,%22,%23,%24,%25,%26,%27,%28,%29,%30,%31}, [%32];" \
        : "=r"((r)[0]),"=r"((r)[1]),"=r"((r)[2]),"=r"((r)[3]),"=r"((r)[4]),"=r"((r)[5]),"=r"((r)[6]),"=r"((r)[7]), \
          "=r"((r)[8]),"=r"((r)[9]),"=r"((r)[10]),"=r"((r)[11]),"=r"((r)[12]),"=r"((r)[13]),"=r"((r)[14]),"=r"((r)[15]), \
          "=r"((r)[16]),"=r"((r)[17]),"=r"((r)[18]),"=r"((r)[19]),"=r"((r)[20]),"=r"((r)[21]),"=r"((r)[22]),"=r"((r)[23]), \
          "=r"((r)[24]),"=r"((r)[25]),"=r"((r)[26]),"=r"((r)[27]),"=r"((r)[28]),"=r"((r)[29]),"=r"((r)[30]),"=r"((r)[31]) \
        : "r"(addr))

__device__ __forceinline__ void mma_tf32_ss(uint32_t d, uint64_t ad, uint64_t bd,
                                            uint32_t idesc, uint32_t en) {
    asm volatile("{\n\t.reg .pred p;\n\tsetp.ne.u32 p, %5, 0;\n\t"
        "tcgen05.mma.cta_group::1.kind::tf32 [%0], %1, %2, %3, {%4,%4,%4,%4}, p;\n\t}"
        :: "r"(d), "l"(ad), "l"(bd), "r"(idesc), "r"(0u), "r"(en) : "memory");
}
#endif

// ---------------- LayerNorm ----------------
__device__ __forceinline__ float warp_sum(float v) {
    #pragma unroll
    for (int o = 16; o > 0; o >>= 1) v += __shfl_xor_sync(0xffffffffu, v, o);
    return v;
}

__global__ void layernorm_kernel(const float* __restrict__ x,
                                 const float* __restrict__ gamma,
                                 const float* __restrict__ beta,
                                 float* __restrict__ out) {
    const int row = blockIdx.x;
    const float* xr = x + (size_t)row * EMB;
    float s = 0.f, s2 = 0.f;
    for (int i = threadIdx.x; i < EMB; i += blockDim.x) {
        float v = xr[i];
        s += v; s2 += v * v;
    }
    s = warp_sum(s); s2 = warp_sum(s2);
    __shared__ float sh[2][8];
    int lane = threadIdx.x & 31, wid = threadIdx.x >> 5;
    if (lane == 0) { sh[0][wid] = s; sh[1][wid] = s2; }
    __syncthreads();
    if (wid == 0) {
        float a = (lane < 8) ? sh[0][lane] : 0.f;
        float b = (lane < 8) ? sh[1][lane] : 0.f;
        a = warp_sum(a); b = warp_sum(b);
        if (lane == 0) { sh[0][0] = a; sh[1][0] = b; }
    }
    __syncthreads();
    float mean = sh[0][0] * (1.0f / EMB);
    float var  = sh[1][0] * (1.0f / EMB) - mean * mean;
    float inv  = rsqrtf(var + 1e-5f);
    float* outr = out + (size_t)row * EMB;
    for (int i = threadIdx.x; i < EMB; i += blockDim.x) {
        outr[i] = gamma[i] * ((xr[i] - mean) * inv) + beta[i];
    }
}

// ---------------- tcgen05 tf32 GEMM: 128x256 tile, BK=32, double-buffered ----------------
#define BM 128
#define BN 256
#define BK 32
#define ABYTES (BM*128)
#define BBYTES (BN*128)
#define BUFBYTES (ABYTES+BBYTES)
#define SMEM_DYN (2*BUFBYTES + 1024)

#define IDESC_TF32 ((1u << 4) | (2u << 7) | (2u << 10) | ((BN / 8) << 17) | ((BM / 16) << 24))

template<bool GELU, bool BIAS, bool RES>
__global__ void __launch_bounds__(256, 2)
tc_gemm(const float* __restrict__ A, const float* __restrict__ B,
        float* __restrict__ C, int M, int N, int K,
        const float* __restrict__ bias, const float* __restrict__ res) {
#if TC_OK
    extern __shared__ char sm_raw[];
    __shared__ uint32_t s_tmem;
    __shared__ __align__(8) uint64_t s_mbar[2];

    const int tid = threadIdx.x, wid = tid >> 5, lane = tid & 31;
    const int bm = blockIdx.y * BM, bn = blockIdx.x * BN;

    uint32_t smb_raw = smem_u32(sm_raw);
    uint32_t smb = (smb_raw + 1023u) & ~1023u;
    char* sm = sm_raw + (smb - smb_raw);
    uint32_t mbar0 = smem_u32(&s_mbar[0]);

    if (wid == 4) {
        asm volatile("tcgen05.alloc.cta_group::1.sync.aligned.shared::cta.b32 [%0], %1;"
                     :: "r"(smem_u32(&s_tmem)), "r"(256) : "memory");
    }
    if (tid == 0) { MBAR_INIT(mbar0, 1); MBAR_INIT(mbar0 + 8, 1); }
    __syncthreads();
    const uint32_t tmem = s_tmem;

    const int KIT = K / BK;
    for (int i = 0; i < KIT; i++) {
        const int buf = i & 1;
        const uint32_t abase = (uint32_t)buf * BUFBYTES;
        const uint32_t bbase = abase + ABYTES;
        if (i >= 2) MBAR_WAIT(mbar0 + 8 * buf, ((i - 2) >> 1) & 1);

        const int k0 = i * BK;
        #pragma unroll
        for (int p = 0; p < 4; p++) {
            int idx = tid + p * 256;
            int m = idx >> 3, kq = idx & 7;
            float4 v = *(const float4*)(A + (size_t)(bm + m) * K + (k0 + kq * 4));
            uint4 t;
            t.x = f2tf32(v.x); t.y = f2tf32(v.y); t.z = f2tf32(v.z); t.w = f2tf32(v.w);
            *(uint4*)(sm + abase + SWZ((uint32_t)(m * 128 + kq * 16))) = t;
        }
        #pragma unroll
        for (int p = 0; p < 8; p++) {
            int idx = tid + p * 256;
            int n = idx & 255, kq = idx >> 8;
            const float* bp = B + (size_t)(k0 + kq * 4) * N + bn + n;
            uint4 t;
            t.x = f2tf32(bp[0]);
            t.y = f2tf32(bp[(size_t)N]);
            t.z = f2tf32(bp[2 * (size_t)N]);
            t.w = f2tf32(bp[3 * (size_t)N]);
            *(uint4*)(sm + bbase + SWZ((uint32_t)(n * 128 + kq * 16))) = t;
        }
        asm volatile("fence.proxy.async.shared::cta;" ::: "memory");
        __syncthreads();

        if (wid == 4) {
            uint64_t ad = make_desc_sw128(smb + abase);
            uint64_t bd = make_desc_sw128(smb + bbase);
            if (elect1()) {
                #pragma unroll
                for (int kk = 0; kk < 4; kk++) {
                    uint32_t en = (i > 0 || kk > 0) ? 1u : 0u;
                    mma_tf32_ss(tmem, ad + kk * 2, bd + kk * 2, IDESC_TF32, en);
                }
                asm volatile("tcgen05.commit.cta_group::1.mbarrier::arrive::one.shared::cluster.b64 [%0];"
                             :: "r"(mbar0 + 8 * buf) : "memory");
            }
        }
    }

    MBAR_WAIT(mbar0 + 8 * ((KIT - 1) & 1), ((KIT - 1) >> 1) & 1);
    asm volatile("tcgen05.fence::after_thread_sync;" ::: "memory");
    __syncthreads();

    #pragma unroll
    for (int h = 0; h < 2; h++) {
        if (wid < 4) {
            #pragma unroll
            for (int c = 0; c < 4; c++) {
                uint32_t r[32];
                LDTM_X32(r, tmem + h * 128 + c * 32);
                asm volatile("tcgen05.wait::ld.sync.aligned;" ::: "memory");
                char* row = sm + (wid * 32 + lane) * 528 + c * 128;
                #pragma unroll
                for (int j = 0; j < 8; j++) {
                    float4 v;
                    v.x = __uint_as_float(r[4 * j + 0]);
                    v.y = __uint_as_float(r[4 * j + 1]);
                    v.z = __uint_as_float(r[4 * j + 2]);
                    v.w = __uint_as_float(r[4 * j + 3]);
                    *(float4*)(row + j * 16) = v;
                }
            }
        }
        __syncthreads();
        #pragma unroll
        for (int p = 0; p < 16; p++) {
            int idx = tid + p * 256;
            int r = idx >> 5, cq = idx & 31;
            float4 v = *(float4*)(sm + r * 528 + cq * 16);
            int n = bn + h * 128 + cq * 4;
            size_t off = (size_t)(bm + r) * N + n;
            if (BIAS) {
                float4 bb = *(const float4*)(bias + n);
                v.x += bb.x; v.y += bb.y; v.z += bb.z; v.w += bb.w;
            }
            if (GELU) {
                v.x = 0.5f * v.x * (1.0f + erff(v.x * 0.7071067811865476f));
                v.y = 0.5f * v.y * (1.0f + erff(v.y * 0.7071067811865476f));
                v.z = 0.5f * v.z * (1.0f + erff(v.z * 0.7071067811865476f));
                v.w = 0.5f * v.w * (1.0f + erff(v.w * 0.7071067811865476f));
            }
            if (RES) {
                float4 rr = *(const float4*)(res + off);
                v.x += rr.x; v.y += rr.y; v.z += rr.z; v.w += rr.w;
            }
            *(float4*)(C + off) = v;
        }
        __syncthreads();
    }

    if (tid == 0) { MBAR_INVAL(mbar0); MBAR_INVAL(mbar0 + 8); }
    if (wid == 4) {
        asm volatile("tcgen05.dealloc.cta_group::1.sync.aligned.b32 %0, %1;" :: "r"(tmem), "r"(256));
    }
#endif
}

// ---------------- tcgen05 flash attention (causal) ----------------
// CTA = 128 queries of one (b,h). 256 threads. TMEM: S cols 0-127, O-partial 128-191.
#define ATT_Q 0
#define ATT_K 32768
#define ATT_V 65536
#define ATT_P 98304
#define ATT_SMEM (163840 + 1024)

#define IDESC_S  ((1u << 4) | (2u << 7) | (2u << 10) | (16u << 17) | (8u << 24))
#define IDESC_PV ((1u << 4) | (2u << 7) | (2u << 10) | ( 8u << 17) | (8u << 24))

__global__ void __launch_bounds__(256, 1)
flash_attn_tc(const float* __restrict__ Q, const float* __restrict__ K,
              const float* __restrict__ V, float* __restrict__ ctx) {
#if TC_OK
    extern __shared__ char sm_raw[];
    __shared__ uint32_t s_tmem;
    __shared__ __align__(8) uint64_t s_mbar[2];

    const int tid = threadIdx.x, wid = tid >> 5, lane = tid & 31;
    const int qti = gridDim.x - 1 - blockIdx.x;   // heavy tiles first
    const int qt  = qti * 128;
    const int bh  = blockIdx.y;
    const int b   = bh >> 4, h = bh & 15;
    const int base = b * SEQ;
    const int hcol = h * DHEAD;

    uint32_t smb_raw = smem_u32(sm_raw);
    uint32_t smb = (smb_raw + 1023u) & ~1023u;
    char* sm = sm_raw + (smb - smb_raw);
    uint32_t mbar0 = smem_u32(&s_mbar[0]);

    if (wid == 4) {
        asm volatile("tcgen05.alloc.cta_group::1.sync.aligned.shared::cta.b32 [%0], %1;"
                     :: "r"(smem_u32(&s_tmem)), "r"(256) : "memory");
    }
    if (tid == 0) { MBAR_INIT(mbar0, 1); MBAR_INIT(mbar0 + 8, 1); }
    __syncthreads();
    const uint32_t tmem = s_tmem;

    // Load Q tile (pre-scaled by 1/sqrt(DH)=0.125), K-major SW128, 2 d-chunks
    #pragma unroll
    for (int p = 0; p < 8; p++) {
        int idx = tid + p * 256;
        int r = idx >> 4, qd = idx & 15;
        float4 v = *(const float4*)(Q + (size_t)(base + qt + r) * EMB + hcol + qd * 4);
        uint4 t;
        t.x = f2tf32(v.x * 0.125f); t.y = f2tf32(v.y * 0.125f);
        t.z = f2tf32(v.z * 0.125f); t.w = f2tf32(v.w * 0.125f);
        *(uint4*)(sm + ATT_Q + (qd >> 3) * 16384 + SWZ((uint32_t)(r * 128 + (qd & 7) * 16))) = t;
    }

    float m = -INFINITY, sum = 0.f, corr = 0.f;
    float o[64];
    #pragma unroll
    for (int i = 0; i < 64; i++) o[i] = 0.f;
    const int qrow = qt + (wid & 3) * 32 + lane;   // valid for wid<4
    const int ntiles = qti + 1;

    for (int t = 0; t < ntiles; t++) {
        const int k0 = t * 128;
        // K tile: rows=key, K-major in d (2 chunks)
        #pragma unroll
        for (int p = 0; p < 8; p++) {
            int idx = tid + p * 256;
            int r = idx >> 4, qd = idx & 15;
            float4 v = *(const float4*)(K + (size_t)(base + k0 + r) * EMB + hcol + qd * 4);
            uint4 tt;
            tt.x = f2tf32(v.x); tt.y = f2tf32(v.y); tt.z = f2tf32(v.z); tt.w = f2tf32(v.w);
            *(uint4*)(sm + ATT_K + (qd >> 3) * 16384 + SWZ((uint32_t)(r * 128 + (qd & 7) * 16))) = tt;
        }
        // V^T tile: rows=d (64), cols=key (4 chunks of 32 keys)
        #pragma unroll
        for (int p = 0; p < 8; p++) {
            int idx = tid + p * 256;
            int d = idx & 63, kq = idx >> 6;     // keys kq*4..+3
            const float* vp = V + (size_t)(base + k0 + kq * 4) * EMB + hcol + d;
            uint4 tt;
            tt.x = f2tf32(vp[0]);
            tt.y = f2tf32(vp[EMB]);
            tt.z = f2tf32(vp[2 * EMB]);
            tt.w = f2tf32(vp[3 * EMB]);
            *(uint4*)(sm + ATT_V + (kq >> 3) * 8192 + SWZ((uint32_t)(d * 128 + (kq & 7) * 16))) = tt;
        }
        asm volatile("fence.proxy.async.shared::cta;" ::: "memory");
        __syncthreads();

        // S = Q @ K^T  (Kdim = 64 = 2 chunks x 4 dispatches)
        if (wid == 4 && elect1()) {
            #pragma unroll
            for (int c = 0; c < 2; c++) {
                uint64_t ad = make_desc_sw128(smb + ATT_Q + c * 16384);
                uint64_t bd = make_desc_sw128(smb + ATT_K + c * 16384);
                #pragma unroll
                for (int kk = 0; kk < 4; kk++)
                    mma_tf32_ss(tmem, ad + kk * 2, bd + kk * 2, IDESC_S, (c | kk) ? 1u : 0u);
            }
            asm volatile("tcgen05.commit.cta_group::1.mbarrier::arrive::one.shared::cluster.b64 [%0];"
                         :: "r"(mbar0) : "memory");
        }
        MBAR_WAIT(mbar0, t & 1);

        if (wid < 4) {
            asm volatile("tcgen05.fence::after_thread_sync;" ::: "memory");
            float s[128];
            uint32_t* su = (uint32_t*)s;
            #pragma unroll
            for (int c = 0; c < 4; c++) LDTM_X32(su + 32 * c, tmem + 32 * c);
            asm volatile("tcgen05.wait::ld.sync.aligned;" ::: "memory");

            if (k0 + 127 > qrow) {
                #pragma unroll
                for (int j = 0; j < 128; j++)
                    if (k0 + j > qrow) s[j] = -INFINITY;
            }
            float mn = m;
            #pragma unroll
            for (int j = 0; j < 128; j++) mn = fmaxf(mn, s[j]);
            corr = __expf(m - mn);
            float ls = 0.f;
            #pragma unroll
            for (int j = 0; j < 128; j++) {
                float pv = __expf(s[j] - mn);
                ls += pv;
                su[j] = f2tf32(pv);
            }
            sum = sum * corr + ls;
            m = mn;

            // write P (tf32) rows=q, 4 key-chunks
            const int r = wid * 32 + lane;
            #pragma unroll
            for (int c = 0; c < 4; c++) {
                #pragma unroll
                for (int jq = 0; jq < 8; jq++) {
                    uint4 tt;
                    tt.x = su[c * 32 + jq * 4 + 0];
                    tt.y = su[c * 32 + jq * 4 + 1];
                    tt.z = su[c * 32 + jq * 4 + 2];
                    tt.w = su[c * 32 + jq * 4 + 3];
                    *(uint4*)(sm + ATT_P + c * 16384 + SWZ((uint32_t)(r * 128 + jq * 16))) = tt;
                }
            }
        }
        asm volatile("fence.proxy.async.shared::cta;" ::: "memory");
        __syncthreads();

        // O_partial = P @ V^T  (Kdim = 128 keys = 4 chunks x 4 dispatches), en=0 fresh
        if (wid == 4 && elect1()) {
            #pragma unroll
            for (int c = 0; c < 4; c++) {
                uint64_t ad = make_desc_sw128(smb + ATT_P + c * 16384);
                uint64_t bd = make_desc_sw128(smb + ATT_V + c * 8192);
                #pragma unroll
                for (int kk = 0; kk < 4; kk++)
                    mma_tf32_ss(tmem + 128, ad + kk * 2, bd + kk * 2, IDESC_PV, (c | kk) ? 1u : 0u);
            }
            asm volatile("tcgen05.commit.cta_group::1.mbarrier::arrive::one.shared::cluster.b64 [%0];"
                         :: "r"(mbar0 + 8) : "memory");
        }
        MBAR_WAIT(mbar0 + 8, t & 1);

        if (wid < 4) {
            asm volatile("tcgen05.fence::after_thread_sync;" ::: "memory");
            uint32_t part[64];
            LDTM_X32(part, tmem + 128);
            LDTM_X32(part + 32, tmem + 160);
            asm volatile("tcgen05.wait::ld.sync.aligned;" ::: "memory");
            #pragma unroll
            for (int i = 0; i < 64; i++)
                o[i] = o[i] * corr + __uint_as_float(part[i]);
        }
    }

    if (wid < 4) {
        float inv = 1.0f / sum;
        float* outp = ctx + (size_t)(base + qrow) * EMB + hcol;
        #pragma unroll
        for (int i = 0; i < 16; i++) {
            float4 v;
            v.x = o[4 * i + 0] * inv;
            v.y = o[4 * i + 1] * inv;
            v.z = o[4 * i + 2] * inv;
            v.w = o[4 * i + 3] * inv;
            *(float4*)(outp + 4 * i) = v;
        }
    }

    __syncthreads();
    if (tid == 0) { MBAR_INVAL(mbar0); MBAR_INVAL(mbar0 + 8); }
    if (wid == 4) {
        asm volatile("tcgen05.dealloc.cta_group::1.sync.aligned.b32 %0, %1;" :: "r"(tmem), "r"(256));
    }
#endif
}

// ---------------- launch ----------------
extern "C" void kernel_launch(void* const* d_in, const int* in_sizes, int n_in,
                              void* d_out, int out_size) {
    const float* x     = (const float*)d_in[0];
    const float* Wq    = (const float*)d_in[1];
    const float* Wk    = (const float*)d_in[2];
    const float* Wv    = (const float*)d_in[3];
    const float* Wo    = (const float*)d_in[4];
    const float* bo    = (const float*)d_in[5];
    const float* W1    = (const float*)d_in[6];
    const float* b1    = (const float*)d_in[7];
    const float* W2    = (const float*)d_in[8];
    const float* b2    = (const float*)d_in[9];
    const float* g1    = (const float*)d_in[10];
    const float* beta1 = (const float*)d_in[11];
    const float* g2    = (const float*)d_in[12];
    const float* beta2 = (const float*)d_in[13];
    float* out = (float*)d_out;

    float *lnx, *q, *k, *v, *ctx, *h, *mid;
    cudaGetSymbolAddress((void**)&lnx, g_lnx);
    cudaGetSymbolAddress((void**)&q,   g_q);
    cudaGetSymbolAddress((void**)&k,   g_k);
    cudaGetSymbolAddress((void**)&v,   g_v);
    cudaGetSymbolAddress((void**)&ctx, g_ctx);
    cudaGetSymbolAddress((void**)&h,   g_h);
    cudaGetSymbolAddress((void**)&mid, g_mid);

    cudaFuncSetAttribute(tc_gemm<false,false,false>, cudaFuncAttributeMaxDynamicSharedMemorySize, SMEM_DYN);
    cudaFuncSetAttribute(tc_gemm<false,true, true >, cudaFuncAttributeMaxDynamicSharedMemorySize, SMEM_DYN);
    cudaFuncSetAttribute(tc_gemm<true, true, false>, cudaFuncAttributeMaxDynamicSharedMemorySize, SMEM_DYN);
    cudaFuncSetAttribute(flash_attn_tc, cudaFuncAttributeMaxDynamicSharedMemorySize, ATT_SMEM);

    dim3 gEE(EMB / BN, MTOT / BM);    // (4, 64)
    dim3 gEF(FFN / BN, MTOT / BM);    // (16, 64)

    layernorm_kernel<<<MTOT, 256>>>(x, g1, beta1, lnx);
    tc_gemm<false,false,false><<<gEE, 256, SMEM_DYN>>>(lnx, Wq, q, MTOT, EMB, EMB, nullptr, nullptr);
    tc_gemm<false,false,false><<<gEE, 256, SMEM_DYN>>>(lnx, Wk, k, MTOT, EMB, EMB, nullptr, nullptr);
    tc_gemm<false,false,false><<<gEE, 256, SMEM_DYN>>>(lnx, Wv, v, MTOT, EMB, EMB, nullptr, nullptr);
    flash_attn_tc<<<dim3(SEQ / 128, BATCH * HEADS), 256, ATT_SMEM>>>(q, k, v, ctx);
    tc_gemm<false,true,true><<<gEE, 256, SMEM_DYN>>>(ctx, Wo, h, MTOT, EMB, EMB, bo, x);
    layernorm_kernel<<<MTOT, 256>>>(h, g2, beta2, lnx);
    tc_gemm<true,true,false><<<gEF, 256, SMEM_DYN>>>(lnx, W1, mid, MTOT, FFN, EMB, b1, nullptr);
    tc_gemm<false,true,true><<<gEE, 256, SMEM_DYN>>>(mid, W2, out, MTOT, EMB, FFN, b2, h);
}

// round 5
// speedup vs baseline: 6.2067x; 1.2420x over previous
#include <cuda_runtime.h>
#include <math.h>
#include <stdint.h>

// Problem constants
#define BATCH 4
#define SEQ   2048
#define EMB   1024
#define HEADS 16
#define DHEAD 64
#define MTOT  (BATCH*SEQ)      // 8192
#define FFN   (4*EMB)          // 4096

#if defined(__CUDA_ARCH__) && (defined(__CUDA_ARCH_FEAT_SM103_ALL) || defined(__CUDA_ARCH_FEAT_SM100_ALL))
#define TC_OK 1
#else
#define TC_OK 0
#endif

// ---------------- scratch (no allocs allowed) ----------------
__device__ float    g_lnx [(size_t)MTOT*EMB];
__device__ float    g_qkv [(size_t)MTOT*3*EMB];
__device__ float    g_ctx [(size_t)MTOT*EMB];
__device__ float    g_h   [(size_t)MTOT*EMB];
__device__ float    g_mid [(size_t)MTOT*FFN];
__device__ uint32_t g_wqkv_t[(size_t)3*EMB*EMB];   // [3072,1024] tf32
__device__ uint32_t g_wo_t  [(size_t)EMB*EMB];     // [1024,1024]
__device__ uint32_t g_w1_t  [(size_t)FFN*EMB];     // [4096,1024]
__device__ uint32_t g_w2_t  [(size_t)EMB*FFN];     // [1024,4096]

// ---------------- helpers ----------------
__device__ __forceinline__ uint32_t smem_u32(const void* p) {
    uint32_t a;
    asm("{ .reg .u64 t; cvta.to.shared.u64 t, %1; cvt.u32.u64 %0, t; }" : "=r"(a) : "l"(p));
    return a;
}
__device__ __forceinline__ uint32_t f2tf32(float f) {
    uint32_t r;
    asm("cvt.rna.tf32.f32 %0, %1;" : "=r"(r) : "f"(f));
    return r;
}
#define SWZ(o) ((o) ^ (((o) >> 3) & 0x70))

#define MBAR_INIT(a, c) asm volatile("mbarrier.init.shared.b64 [%0], %1;" :: "r"(a), "r"(c) : "memory")
#define MBAR_INVAL(a)   asm volatile("mbarrier.inval.shared.b64 [%0];" :: "r"(a) : "memory")
#define MBAR_WAIT(a, ph) do { \
    uint32_t _m = (a); uint32_t _p = (ph); uint32_t _d; \
    asm volatile("{ .reg .pred p; mbarrier.try_wait.parity.acquire.cta.shared::cta.b64 p, [%1], %2; selp.b32 %0,1,0,p; }" \
        : "=r"(_d) : "r"(_m), "r"(_p) : "memory"); \
    if (!_d) { \
        asm volatile("{ .reg .pred P1; WL_%=: mbarrier.try_wait.parity.acquire.cta.shared::cta.b64 P1, [%0], %1, 0x989680; @P1 bra.uni WD_%=; bra.uni WL_%=; WD_%=: }" \
            :: "r"(_m), "r"(_p) : "memory"); \
    } } while (0)

#if TC_OK
__device__ __forceinline__ uint32_t elect1() {
    uint32_t p;
    asm volatile("{ .reg .pred p; elect.sync _|p, 0xFFFFFFFF; selp.b32 %0,1,0,p; }" : "=r"(p));
    return p;
}
__device__ __forceinline__ uint64_t make_desc_sw128(uint32_t addr) {
    const uint64_t base = (2ull << 61) | (1ull << 46) | (64ull << 32) | (1ull << 16);
    return base | ((uint64_t)(addr >> 4) & 0x3FFF);
}
#define LDTM_X32(r, addr) \
    asm volatile("tcgen05.ld.sync.aligned.32x32b.x32.b32 " \
        "{%0,%1,%2,%3,%4,%5,%6,%7,%8,%9,%10,%11,%12,%13,%14,%15," \
        "%16,%17,%18,%19,%20,%21,%22,%23,%24,%25,%26,%27,%28,%29,%30,%31}, [%32];" \
        : "=r"((r)[0]),"=r"((r)[1]),"=r"((r)[2]),"=r"((r)[3]),"=r"((r)[4]),"=r"((r)[5]),"=r"((r)[6]),"=r"((r)[7]), \
          "=r"((r)[8]),"=r"((r)[9]),"=r"((r)[10]),"=r"((r)[11]),"=r"((r)[12]),"=r"((r)[13]),"=r"((r)[14]),"=r"((r)[15]), \
          "=r"((r)[16]),"=r"((r)[17]),"=r"((r)[18]),"=r"((r)[19]),"=r"((r)[20]),"=r"((r)[21]),"=r"((r)[22]),"=r"((r)[23]), \
          "=r"((r)[24]),"=r"((r)[25]),"=r"((r)[26]),"=r"((r)[27]),"=r"((r)[28]),"=r"((r)[29]),"=r"((r)[30]),"=r"((r)[31]) \
        : "r"(addr))

__device__ __forceinline__ void mma_tf32_ss(uint32_t d, uint64_t ad, uint64_t bd,
                                            uint32_t idesc, uint32_t en) {
    asm volatile("{\n\t.reg .pred p;\n\tsetp.ne.u32 p, %5, 0;\n\t"
        "tcgen05.mma.cta_group::1.kind::tf32 [%0], %1, %2, %3, {%4,%4,%4,%4}, p;\n\t}"
        :: "r"(d), "l"(ad), "l"(bd), "r"(idesc), "r"(0u), "r"(en) : "memory");
}
#endif

// ---------------- weight prep: W[K,N] fp32 -> WT[N,K] tf32 ----------------
__global__ void transpose_cvt_kernel(const float* __restrict__ W, uint32_t* __restrict__ WT,
                                     int K, int N) {
    __shared__ float t[32][33];
    const int n0 = blockIdx.x * 32, k0 = blockIdx.y * 32;
    const int tx = threadIdx.x & 31, ty = threadIdx.x >> 5;   // 256 thr
    #pragma unroll
    for (int j = 0; j < 32; j += 8)
        t[ty + j][tx] = W[(size_t)(k0 + ty + j) * N + n0 + tx];
    __syncthreads();
    #pragma unroll
    for (int j = 0; j < 32; j += 8)
        WT[(size_t)(n0 + ty + j) * K + k0 + tx] = f2tf32(t[tx][ty + j]);
}

// ---------------- LayerNorm ----------------
__device__ __forceinline__ float warp_sum(float v) {
    #pragma unroll
    for (int o = 16; o > 0; o >>= 1) v += __shfl_xor_sync(0xffffffffu, v, o);
    return v;
}

__global__ void layernorm_kernel(const float* __restrict__ x,
                                 const float* __restrict__ gamma,
                                 const float* __restrict__ beta,
                                 float* __restrict__ out) {
    const int row = blockIdx.x;
    const float* xr = x + (size_t)row * EMB;
    float s = 0.f, s2 = 0.f;
    for (int i = threadIdx.x; i < EMB; i += blockDim.x) {
        float v = xr[i];
        s += v; s2 += v * v;
    }
    s = warp_sum(s); s2 = warp_sum(s2);
    __shared__ float sh[2][8];
    int lane = threadIdx.x & 31, wid = threadIdx.x >> 5;
    if (lane == 0) { sh[0][wid] = s; sh[1][wid] = s2; }
    __syncthreads();
    if (wid == 0) {
        float a = (lane < 8) ? sh[0][lane] : 0.f;
        float b = (lane < 8) ? sh[1][lane] : 0.f;
        a = warp_sum(a); b = warp_sum(b);
        if (lane == 0) { sh[0][0] = a; sh[1][0] = b; }
    }
    __syncthreads();
    float mean = sh[0][0] * (1.0f / EMB);
    float var  = sh[1][0] * (1.0f / EMB) - mean * mean;
    float inv  = rsqrtf(var + 1e-5f);
    float* outr = out + (size_t)row * EMB;
    for (int i = threadIdx.x; i < EMB; i += blockDim.x) {
        outr[i] = gamma[i] * ((xr[i] - mean) * inv) + beta[i];
    }
}

// ---------------- tcgen05 tf32 GEMM: 128x256 tile, BK=32, reg-prefetch pipeline ----------------
// A: fp32 [M,K] row-major (cvt on load). BT: tf32 [N,K] row-major (pre-converted).
#define BM 128
#define BN 256
#define BK 32
#define ABYTES (BM*128)
#define BBYTES (BN*128)
#define BUFBYTES (ABYTES+BBYTES)
#define SMEM_DYN (2*BUFBYTES + 1024)

#define IDESC_TF32 ((1u << 4) | (2u << 7) | (2u << 10) | ((BN / 8) << 17) | ((BM / 16) << 24))

template<bool GELU, bool BIAS, bool RES>
__global__ void __launch_bounds__(256, 1)
tc_gemm(const float* __restrict__ A, const uint32_t* __restrict__ BT,
        float* __restrict__ C, int M, int N, int K,
        const float* __restrict__ bias, const float* __restrict__ res) {
#if TC_OK
    extern __shared__ char sm_raw[];
    __shared__ uint32_t s_tmem;
    __shared__ __align__(8) uint64_t s_mbar[2];

    const int tid = threadIdx.x, wid = tid >> 5, lane = tid & 31;
    const int bm = blockIdx.y * BM, bn = blockIdx.x * BN;

    uint32_t smb_raw = smem_u32(sm_raw);
    uint32_t smb = (smb_raw + 1023u) & ~1023u;
    char* sm = sm_raw + (smb - smb_raw);
    uint32_t mbar0 = smem_u32(&s_mbar[0]);

    if (wid == 4) {
        asm volatile("tcgen05.alloc.cta_group::1.sync.aligned.shared::cta.b32 [%0], %1;"
                     :: "r"(smem_u32(&s_tmem)), "r"(256) : "memory");
    }
    if (tid == 0) { MBAR_INIT(mbar0, 1); MBAR_INIT(mbar0 + 8, 1); }
    __syncthreads();
    const uint32_t tmem = s_tmem;

    // per-thread load/store coordinates (fixed)
    const int am = tid >> 3, akq = tid & 7;              // A: rows 0..127 via 2 steps? (1024 granules/256 = 4)
    const uint32_t a_sw0 = SWZ((uint32_t)(am * 128 + akq * 16));
    const int KIT = K / BK;

    uint4 ra[4], rb[8];
    // A granules: idx = tid + p*256 -> m = idx>>3 in {am, am+32, am+64, am+96}, kq = akq
    #define LOAD_A(i) do { \
        const float* ap = A + (size_t)(bm + am) * K + (i) * BK + akq * 4; \
        _Pragma("unroll") \
        for (int p = 0; p < 4; p++) { \
            float4 v = *(const float4*)(ap + (size_t)(p * 32) * K); \
            ra[p].x = f2tf32(v.x); ra[p].y = f2tf32(v.y); \
            ra[p].z = f2tf32(v.z); ra[p].w = f2tf32(v.w); \
        } } while (0)
    // B granules: idx = tid + p*256 -> n = idx>>3 in {am+32p}, kq = akq  (row = n, 128B/row)
    #define LOAD_B(i) do { \
        const uint32_t* bp = BT + (size_t)(bn + am) * K + (i) * BK + akq * 4; \
        _Pragma("unroll") \
        for (int p = 0; p < 8; p++) \
            rb[p] = *(const uint4*)(bp + (size_t)(p * 32) * K); \
        } while (0)

    LOAD_A(0); LOAD_B(0);

    for (int i = 0; i < KIT; i++) {
        const int buf = i & 1;
        const uint32_t abase = (uint32_t)buf * BUFBYTES;
        const uint32_t bbase = abase + ABYTES;
        if (i >= 2) MBAR_WAIT(mbar0 + 8 * buf, ((i - 2) >> 1) & 1);

        #pragma unroll
        for (int p = 0; p < 4; p++)
            *(uint4*)(sm + abase + p * 4096 + a_sw0) = ra[p];
        #pragma unroll
        for (int p = 0; p < 8; p++)
            *(uint4*)(sm + bbase + p * 4096 + a_sw0) = rb[p];

        asm volatile("fence.proxy.async.shared::cta;" ::: "memory");
        __syncthreads();

        if (wid == 4) {
            uint64_t ad = make_desc_sw128(smb + abase);
            uint64_t bd = make_desc_sw128(smb + bbase);
            if (elect1()) {
                #pragma unroll
                for (int kk = 0; kk < 4; kk++) {
                    uint32_t en = (i > 0 || kk > 0) ? 1u : 0u;
                    mma_tf32_ss(tmem, ad + kk * 2, bd + kk * 2, IDESC_TF32, en);
                }
                asm volatile("tcgen05.commit.cta_group::1.mbarrier::arrive::one.shared::cluster.b64 [%0];"
                             :: "r"(mbar0 + 8 * buf) : "memory");
            }
        }
        if (i + 1 < KIT) { LOAD_A(i + 1); LOAD_B(i + 1); }
    }

    MBAR_WAIT(mbar0 + 8 * ((KIT - 1) & 1), ((KIT - 1) >> 1) & 1);
    asm volatile("tcgen05.fence::after_thread_sync;" ::: "memory");
    __syncthreads();

    #pragma unroll
    for (int h = 0; h < 2; h++) {
        if (wid < 4) {
            #pragma unroll
            for (int c = 0; c < 4; c++) {
                uint32_t r[32];
                LDTM_X32(r, tmem + h * 128 + c * 32);
                asm volatile("tcgen05.wait::ld.sync.aligned;" ::: "memory");
                char* row = sm + (wid * 32 + lane) * 528 + c * 128;
                #pragma unroll
                for (int j = 0; j < 8; j++) {
                    float4 v;
                    v.x = __uint_as_float(r[4 * j + 0]);
                    v.y = __uint_as_float(r[4 * j + 1]);
                    v.z = __uint_as_float(r[4 * j + 2]);
                    v.w = __uint_as_float(r[4 * j + 3]);
                    *(float4*)(row + j * 16) = v;
                }
            }
        }
        __syncthreads();
        #pragma unroll
        for (int p = 0; p < 16; p++) {
            int idx = tid + p * 256;
            int r = idx >> 5, cq = idx & 31;
            float4 v = *(float4*)(sm + r * 528 + cq * 16);
            int n = bn + h * 128 + cq * 4;
            size_t off = (size_t)(bm + r) * N + n;
            if (BIAS) {
                float4 bb = *(const float4*)(bias + n);
                v.x += bb.x; v.y += bb.y; v.z += bb.z; v.w += bb.w;
            }
            if (GELU) {
                v.x = 0.5f * v.x * (1.0f + erff(v.x * 0.7071067811865476f));
                v.y = 0.5f * v.y * (1.0f + erff(v.y * 0.7071067811865476f));
                v.z = 0.5f * v.z * (1.0f + erff(v.z * 0.7071067811865476f));
                v.w = 0.5f * v.w * (1.0f + erff(v.w * 0.7071067811865476f));
            }
            if (RES) {
                float4 rr = *(const float4*)(res + off);
                v.x += rr.x; v.y += rr.y; v.z += rr.z; v.w += rr.w;
            }
            *(float4*)(C + off) = v;
        }
        __syncthreads();
    }

    if (tid == 0) { MBAR_INVAL(mbar0); MBAR_INVAL(mbar0 + 8); }
    if (wid == 4) {
        asm volatile("tcgen05.dealloc.cta_group::1.sync.aligned.b32 %0, %1;" :: "r"(tmem), "r"(256));
    }
    #undef LOAD_A
    #undef LOAD_B
#endif
}

// ---------------- tcgen05 flash attention (causal), QKV packed [M,3072] ----------------
#define QKVS (3*EMB)
#define ATT_Q 0
#define ATT_K 32768
#define ATT_V 65536
#define ATT_P 98304
#define ATT_SMEM (163840 + 1024)

#define IDESC_S  ((1u << 4) | (2u << 7) | (2u << 10) | (16u << 17) | (8u << 24))
#define IDESC_PV ((1u << 4) | (2u << 7) | (2u << 10) | ( 8u << 17) | (8u << 24))

__global__ void __launch_bounds__(256, 1)
flash_attn_tc(const float* __restrict__ QKV, float* __restrict__ ctx) {
#if TC_OK
    extern __shared__ char sm_raw[];
    __shared__ uint32_t s_tmem;
    __shared__ __align__(8) uint64_t s_mbar[2];

    const int tid = threadIdx.x, wid = tid >> 5, lane = tid & 31;
    const int qti = gridDim.x - 1 - blockIdx.x;
    const int qt  = qti * 128;
    const int bh  = blockIdx.y;
    const int b   = bh >> 4, h = bh & 15;
    const int base = b * SEQ;
    const int hcol = h * DHEAD;

    uint32_t smb_raw = smem_u32(sm_raw);
    uint32_t smb = (smb_raw + 1023u) & ~1023u;
    char* sm = sm_raw + (smb - smb_raw);
    uint32_t mbar0 = smem_u32(&s_mbar[0]);

    if (wid == 4) {
        asm volatile("tcgen05.alloc.cta_group::1.sync.aligned.shared::cta.b32 [%0], %1;"
                     :: "r"(smem_u32(&s_tmem)), "r"(256) : "memory");
    }
    if (tid == 0) { MBAR_INIT(mbar0, 1); MBAR_INIT(mbar0 + 8, 1); }
    __syncthreads();
    const uint32_t tmem = s_tmem;

    // Load Q tile (pre-scaled), K-major SW128, 2 d-chunks
    #pragma unroll
    for (int p = 0; p < 8; p++) {
        int idx = tid + p * 256;
        int r = idx >> 4, qd = idx & 15;
        float4 v = *(const float4*)(QKV + (size_t)(base + qt + r) * QKVS + hcol + qd * 4);
        uint4 t;
        t.x = f2tf32(v.x * 0.125f); t.y = f2tf32(v.y * 0.125f);
        t.z = f2tf32(v.z * 0.125f); t.w = f2tf32(v.w * 0.125f);
        *(uint4*)(sm + ATT_Q + (qd >> 3) * 16384 + SWZ((uint32_t)(r * 128 + (qd & 7) * 16))) = t;
    }

    float m = -INFINITY, sum = 0.f, corr = 0.f;
    float o[64];
    #pragma unroll
    for (int i = 0; i < 64; i++) o[i] = 0.f;
    const int qrow = qt + (wid & 3) * 32 + lane;
    const int ntiles = qti + 1;

    for (int t = 0; t < ntiles; t++) {
        const int k0 = t * 128;
        #pragma unroll
        for (int p = 0; p < 8; p++) {
            int idx = tid + p * 256;
            int r = idx >> 4, qd = idx & 15;
            float4 v = *(const float4*)(QKV + (size_t)(base + k0 + r) * QKVS + EMB + hcol + qd * 4);
            uint4 tt;
            tt.x = f2tf32(v.x); tt.y = f2tf32(v.y); tt.z = f2tf32(v.z); tt.w = f2tf32(v.w);
            *(uint4*)(sm + ATT_K + (qd >> 3) * 16384 + SWZ((uint32_t)(r * 128 + (qd & 7) * 16))) = tt;
        }
        #pragma unroll
        for (int p = 0; p < 8; p++) {
            int idx = tid + p * 256;
            int d = idx & 63, kq = idx >> 6;
            const float* vp = QKV + (size_t)(base + k0 + kq * 4) * QKVS + 2 * EMB + hcol + d;
            uint4 tt;
            tt.x = f2tf32(vp[0]);
            tt.y = f2tf32(vp[QKVS]);
            tt.z = f2tf32(vp[2 * QKVS]);
            tt.w = f2tf32(vp[3 * QKVS]);
            *(uint4*)(sm + ATT_V + (kq >> 3) * 8192 + SWZ((uint32_t)(d * 128 + (kq & 7) * 16))) = tt;
        }
        asm volatile("fence.proxy.async.shared::cta;" ::: "memory");
        __syncthreads();

        if (wid == 4 && elect1()) {
            #pragma unroll
            for (int c = 0; c < 2; c++) {
                uint64_t ad = make_desc_sw128(smb + ATT_Q + c * 16384);
                uint64_t bd = make_desc_sw128(smb + ATT_K + c * 16384);
                #pragma unroll
                for (int kk = 0; kk < 4; kk++)
                    mma_tf32_ss(tmem, ad + kk * 2, bd + kk * 2, IDESC_S, (c | kk) ? 1u : 0u);
            }
            asm volatile("tcgen05.commit.cta_group::1.mbarrier::arrive::one.shared::cluster.b64 [%0];"
                         :: "r"(mbar0) : "memory");
        }
        MBAR_WAIT(mbar0, t & 1);

        if (wid < 4) {
            asm volatile("tcgen05.fence::after_thread_sync;" ::: "memory");
            float s[128];
            uint32_t* su = (uint32_t*)s;
            #pragma unroll
            for (int c = 0; c < 4; c++) LDTM_X32(su + 32 * c, tmem + 32 * c);
            asm volatile("tcgen05.wait::ld.sync.aligned;" ::: "memory");

            if (k0 + 127 > qrow) {
                #pragma unroll
                for (int j = 0; j < 128; j++)
                    if (k0 + j > qrow) s[j] = -INFINITY;
            }
            float mn = m;
            #pragma unroll
            for (int j = 0; j < 128; j++) mn = fmaxf(mn, s[j]);
            corr = __expf(m - mn);
            float ls = 0.f;
            #pragma unroll
            for (int j = 0; j < 128; j++) {
                float pv = __expf(s[j] - mn);
                ls += pv;
                su[j] = f2tf32(pv);
            }
            sum = sum * corr + ls;
            m = mn;

            const int r = wid * 32 + lane;
            #pragma unroll
            for (int c = 0; c < 4; c++) {
                #pragma unroll
                for (int jq = 0; jq < 8; jq++) {
                    uint4 tt;
                    tt.x = su[c * 32 + jq * 4 + 0];
                    tt.y = su[c * 32 + jq * 4 + 1];
                    tt.z = su[c * 32 + jq * 4 + 2];
                    tt.w = su[c * 32 + jq * 4 + 3];
                    *(uint4*)(sm + ATT_P + c * 16384 + SWZ((uint32_t)(r * 128 + jq * 16))) = tt;
                }
            }
        }
        asm volatile("fence.proxy.async.shared::cta;" ::: "memory");
        __syncthreads();

        if (wid == 4 && elect1()) {
            #pragma unroll
            for (int c = 0; c < 4; c++) {
                uint64_t ad = make_desc_sw128(smb + ATT_P + c * 16384);
                uint64_t bd = make_desc_sw128(smb + ATT_V + c * 8192);
                #pragma unroll
                for (int kk = 0; kk < 4; kk++)
                    mma_tf32_ss(tmem + 128, ad + kk * 2, bd + kk * 2, IDESC_PV, (c | kk) ? 1u : 0u);
            }
            asm volatile("tcgen05.commit.cta_group::1.mbarrier::arrive::one.shared::cluster.b64 [%0];"
                         :: "r"(mbar0 + 8) : "memory");
        }
        MBAR_WAIT(mbar0 + 8, t & 1);

        if (wid < 4) {
            asm volatile("tcgen05.fence::after_thread_sync;" ::: "memory");
            uint32_t part[64];
            LDTM_X32(part, tmem + 128);
            LDTM_X32(part + 32, tmem + 160);
            asm volatile("tcgen05.wait::ld.sync.aligned;" ::: "memory");
            #pragma unroll
            for (int i = 0; i < 64; i++)
                o[i] = o[i] * corr + __uint_as_float(part[i]);
        }
    }

    if (wid < 4) {
        float inv = 1.0f / sum;
        float* outp = ctx + (size_t)(base + qrow) * EMB + hcol;
        #pragma unroll
        for (int i = 0; i < 16; i++) {
            float4 v;
            v.x = o[4 * i + 0] * inv;
            v.y = o[4 * i + 1] * inv;
            v.z = o[4 * i + 2] * inv;
            v.w = o[4 * i + 3] * inv;
            *(float4*)(outp + 4 * i) = v;
        }
    }

    __syncthreads();
    if (tid == 0) { MBAR_INVAL(mbar0); MBAR_INVAL(mbar0 + 8); }
    if (wid == 4) {
        asm volatile("tcgen05.dealloc.cta_group::1.sync.aligned.b32 %0, %1;" :: "r"(tmem), "r"(256));
    }
#endif
}

// ---------------- launch ----------------
extern "C" void kernel_launch(void* const* d_in, const int* in_sizes, int n_in,
                              void* d_out, int out_size) {
    const float* x     = (const float*)d_in[0];
    const float* Wq    = (const float*)d_in[1];
    const float* Wk    = (const float*)d_in[2];
    const float* Wv    = (const float*)d_in[3];
    const float* Wo    = (const float*)d_in[4];
    const float* bo    = (const float*)d_in[5];
    const float* W1    = (const float*)d_in[6];
    const float* b1    = (const float*)d_in[7];
    const float* W2    = (const float*)d_in[8];
    const float* b2    = (const float*)d_in[9];
    const float* g1    = (const float*)d_in[10];
    const float* beta1 = (const float*)d_in[11];
    const float* g2    = (const float*)d_in[12];
    const float* beta2 = (const float*)d_in[13];
    float* out = (float*)d_out;

    float *lnx, *qkv, *ctx, *h, *mid;
    uint32_t *wqkv_t, *wo_t, *w1_t, *w2_t;
    cudaGetSymbolAddress((void**)&lnx,    g_lnx);
    cudaGetSymbolAddress((void**)&qkv,    g_qkv);
    cudaGetSymbolAddress((void**)&ctx,    g_ctx);
    cudaGetSymbolAddress((void**)&h,      g_h);
    cudaGetSymbolAddress((void**)&mid,    g_mid);
    cudaGetSymbolAddress((void**)&wqkv_t, g_wqkv_t);
    cudaGetSymbolAddress((void**)&wo_t,   g_wo_t);
    cudaGetSymbolAddress((void**)&w1_t,   g_w1_t);
    cudaGetSymbolAddress((void**)&w2_t,   g_w2_t);

    cudaFuncSetAttribute(tc_gemm<false,false,false>, cudaFuncAttributeMaxDynamicSharedMemorySize, SMEM_DYN);
    cudaFuncSetAttribute(tc_gemm<false,true, true >, cudaFuncAttributeMaxDynamicSharedMemorySize, SMEM_DYN);
    cudaFuncSetAttribute(tc_gemm<true, true, false>, cudaFuncAttributeMaxDynamicSharedMemorySize, SMEM_DYN);
    cudaFuncSetAttribute(flash_attn_tc, cudaFuncAttributeMaxDynamicSharedMemorySize, ATT_SMEM);

    // weight prep (tf32, transposed [N,K])
    dim3 t256(256);
    transpose_cvt_kernel<<<dim3(EMB/32, EMB/32), t256>>>(Wq, wqkv_t,                EMB, EMB);
    transpose_cvt_kernel<<<dim3(EMB/32, EMB/32), t256>>>(Wk, wqkv_t + (size_t)EMB*EMB,   EMB, EMB);
    transpose_cvt_kernel<<<dim3(EMB/32, EMB/32), t256>>>(Wv, wqkv_t + (size_t)2*EMB*EMB, EMB, EMB);
    transpose_cvt_kernel<<<dim3(EMB/32, EMB/32), t256>>>(Wo, wo_t, EMB, EMB);
    transpose_cvt_kernel<<<dim3(FFN/32, EMB/32), t256>>>(W1, w1_t, EMB, FFN);
    transpose_cvt_kernel<<<dim3(EMB/32, FFN/32), t256>>>(W2, w2_t, FFN, EMB);

    layernorm_kernel<<<MTOT, 256>>>(x, g1, beta1, lnx);
    // fused QKV: [8192, 3072]
    tc_gemm<false,false,false><<<dim3(3*EMB/BN, MTOT/BM), 256, SMEM_DYN>>>(
        lnx, wqkv_t, qkv, MTOT, 3*EMB, EMB, nullptr, nullptr);
    flash_attn_tc<<<dim3(SEQ/128, BATCH*HEADS), 256, ATT_SMEM>>>(qkv, ctx);
    tc_gemm<false,true,true><<<dim3(EMB/BN, MTOT/BM), 256, SMEM_DYN>>>(
        ctx, wo_t, h, MTOT, EMB, EMB, bo, x);
    layernorm_kernel<<<MTOT, 256>>>(h, g2, beta2, lnx);
    tc_gemm<true,true,false><<<dim3(FFN/BN, MTOT/BM), 256, SMEM_DYN>>>(
        lnx, w1_t, mid, MTOT, FFN, EMB, b1, nullptr);
    tc_gemm<false,true,true><<<dim3(EMB/BN, MTOT/BM), 256, SMEM_DYN>>>(
        mid, w2_t, out, MTOT, EMB, FFN, b2, h);
}

// round 6
// speedup vs baseline: 8.6434x; 1.3926x over previous
#include <cuda_runtime.h>
#include <math.h>
#include <stdint.h>

// Problem constants
#define BATCH 4
#define SEQ   2048
#define EMB   1024
#define HEADS 16
#define DHEAD 64
#define MTOT  (BATCH*SEQ)      // 8192
#define FFN   (4*EMB)          // 4096

#if defined(__CUDA_ARCH__) && (defined(__CUDA_ARCH_FEAT_SM103_ALL) || defined(__CUDA_ARCH_FEAT_SM100_ALL))
#define TC_OK 1
#else
#define TC_OK 0
#endif

// ---------------- scratch (no allocs allowed) ----------------
__device__ uint32_t g_lnx [(size_t)MTOT*EMB];       // tf32
__device__ uint32_t g_qkv [(size_t)MTOT*3*EMB];     // tf32
__device__ uint32_t g_ctx [(size_t)MTOT*EMB];       // tf32
__device__ float    g_h   [(size_t)MTOT*EMB];       // fp32 (residual + LN input)
__device__ uint32_t g_mid [(size_t)MTOT*FFN];       // tf32
__device__ uint32_t g_wqkv_t[(size_t)3*EMB*EMB];    // [3072,1024] tf32
__device__ uint32_t g_wo_t  [(size_t)EMB*EMB];
__device__ uint32_t g_w1_t  [(size_t)FFN*EMB];
__device__ uint32_t g_w2_t  [(size_t)EMB*FFN];

// ---------------- helpers ----------------
__device__ __forceinline__ uint32_t smem_u32(const void* p) {
    uint32_t a;
    asm("{ .reg .u64 t; cvta.to.shared.u64 t, %1; cvt.u32.u64 %0, t; }" : "=r"(a) : "l"(p));
    return a;
}
__device__ __forceinline__ uint32_t f2tf32(float f) {
    uint32_t r;
    asm("cvt.rna.tf32.f32 %0, %1;" : "=r"(r) : "f"(f));
    return r;
}
#define SWZ(o) ((o) ^ (((o) >> 3) & 0x70))

#define MBAR_INIT(a, c) asm volatile("mbarrier.init.shared.b64 [%0], %1;" :: "r"(a), "r"(c) : "memory")
#define MBAR_INVAL(a)   asm volatile("mbarrier.inval.shared.b64 [%0];" :: "r"(a) : "memory")
#define MBAR_WAIT(a, ph) do { \
    uint32_t _m = (a); uint32_t _p = (ph); uint32_t _d; \
    asm volatile("{ .reg .pred p; mbarrier.try_wait.parity.acquire.cta.shared::cta.b64 p, [%1], %2; selp.b32 %0,1,0,p; }" \
        : "=r"(_d) : "r"(_m), "r"(_p) : "memory"); \
    if (!_d) { \
        asm volatile("{ .reg .pred P1; WL_%=: mbarrier.try_wait.parity.acquire.cta.shared::cta.b64 P1, [%0], %1, 0x989680; @P1 bra.uni WD_%=; bra.uni WL_%=; WD_%=: }" \
            :: "r"(_m), "r"(_p) : "memory"); \
    } } while (0)

#define CPA16(dst, src) asm volatile("cp.async.cg.shared.global [%0], [%1], 16;" :: "r"(dst), "l"(src) : "memory")
#define CPA_COMMIT() asm volatile("cp.async.commit_group;" ::: "memory")
#define CPA_WAIT2()  asm volatile("cp.async.wait_group 2;" ::: "memory")

#if TC_OK
__device__ __forceinline__ uint32_t elect1() {
    uint32_t p;
    asm volatile("{ .reg .pred p; elect.sync _|p, 0xFFFFFFFF; selp.b32 %0,1,0,p; }" : "=r"(p));
    return p;
}
__device__ __forceinline__ uint64_t make_desc_sw128(uint32_t addr) {
    const uint64_t base = (2ull << 61) | (1ull << 46) | (64ull << 32) | (1ull << 16);
    return base | ((uint64_t)(addr >> 4) & 0x3FFF);
}
#define LDTM_X32(r, addr) \
    asm volatile("tcgen05.ld.sync.aligned.32x32b.x32.b32 " \
        "{%0,%1,%2,%3,%4,%5,%6,%7,%8,%9,%10,%11,%12,%13,%14,%15," \
        "%16,%17,%18,%19,%20,%21,%22,%23,%24,%25,%26,%27,%28,%29,%30,%31}, [%32];" \
        : "=r"((r)[0]),"=r"((r)[1]),"=r"((r)[2]),"=r"((r)[3]),"=r"((r)[4]),"=r"((r)[5]),"=r"((r)[6]),"=r"((r)[7]), \
          "=r"((r)[8]),"=r"((r)[9]),"=r"((r)[10]),"=r"((r)[11]),"=r"((r)[12]),"=r"((r)[13]),"=r"((r)[14]),"=r"((r)[15]), \
          "=r"((r)[16]),"=r"((r)[17]),"=r"((r)[18]),"=r"((r)[19]),"=r"((r)[20]),"=r"((r)[21]),"=r"((r)[22]),"=r"((r)[23]), \
          "=r"((r)[24]),"=r"((r)[25]),"=r"((r)[26]),"=r"((r)[27]),"=r"((r)[28]),"=r"((r)[29]),"=r"((r)[30]),"=r"((r)[31]) \
        : "r"(addr))

__device__ __forceinline__ void mma_tf32_ss(uint32_t d, uint64_t ad, uint64_t bd,
                                            uint32_t idesc, uint32_t en) {
    asm volatile("{\n\t.reg .pred p;\n\tsetp.ne.u32 p, %5, 0;\n\t"
        "tcgen05.mma.cta_group::1.kind::tf32 [%0], %1, %2, %3, {%4,%4,%4,%4}, p;\n\t}"
        :: "r"(d), "l"(ad), "l"(bd), "r"(idesc), "r"(0u), "r"(en) : "memory");
}
#endif

// ---------------- weight prep: W[K,N] fp32 -> WT[N,K] tf32 ----------------
__global__ void transpose_cvt_kernel(const float* __restrict__ W, uint32_t* __restrict__ WT,
                                     int K, int N) {
    __shared__ float t[32][33];
    const int n0 = blockIdx.x * 32, k0 = blockIdx.y * 32;
    const int tx = threadIdx.x & 31, ty = threadIdx.x >> 5;
    #pragma unroll
    for (int j = 0; j < 32; j += 8)
        t[ty + j][tx] = W[(size_t)(k0 + ty + j) * N + n0 + tx];
    __syncthreads();
    #pragma unroll
    for (int j = 0; j < 32; j += 8)
        WT[(size_t)(n0 + ty + j) * K + k0 + tx] = f2tf32(t[tx][ty + j]);
}

// ---------------- LayerNorm -> tf32 out ----------------
__device__ __forceinline__ float warp_sum(float v) {
    #pragma unroll
    for (int o = 16; o > 0; o >>= 1) v += __shfl_xor_sync(0xffffffffu, v, o);
    return v;
}

__global__ void layernorm_kernel(const float* __restrict__ x,
                                 const float* __restrict__ gamma,
                                 const float* __restrict__ beta,
                                 uint32_t* __restrict__ out) {
    const int row = blockIdx.x;
    const float* xr = x + (size_t)row * EMB;
    float s = 0.f, s2 = 0.f;
    for (int i = threadIdx.x; i < EMB; i += blockDim.x) {
        float v = xr[i];
        s += v; s2 += v * v;
    }
    s = warp_sum(s); s2 = warp_sum(s2);
    __shared__ float sh[2][8];
    int lane = threadIdx.x & 31, wid = threadIdx.x >> 5;
    if (lane == 0) { sh[0][wid] = s; sh[1][wid] = s2; }
    __syncthreads();
    if (wid == 0) {
        float a = (lane < 8) ? sh[0][lane] : 0.f;
        float b = (lane < 8) ? sh[1][lane] : 0.f;
        a = warp_sum(a); b = warp_sum(b);
        if (lane == 0) { sh[0][0] = a; sh[1][0] = b; }
    }
    __syncthreads();
    float mean = sh[0][0] * (1.0f / EMB);
    float var  = sh[1][0] * (1.0f / EMB) - mean * mean;
    float inv  = rsqrtf(var + 1e-5f);
    uint32_t* outr = out + (size_t)row * EMB;
    for (int i = threadIdx.x; i < EMB; i += blockDim.x) {
        outr[i] = f2tf32(gamma[i] * ((xr[i] - mean) * inv) + beta[i]);
    }
}

// ---------------- tcgen05 tf32 GEMM: 128x256, BK=32, 3-stage cp.async pipeline ----------------
// A: tf32 [M,K] row-major. BT: tf32 [N,K] row-major.
#define BM 128
#define BN 256
#define BK 32
#define ABYTES (BM*128)
#define BBYTES (BN*128)
#define BUFBYTES (ABYTES+BBYTES)
#define NSTAGE 3
#define SMEM_DYN (NSTAGE*BUFBYTES + 1024)

#define IDESC_TF32 ((1u << 4) | (2u << 7) | (2u << 10) | ((BN / 8) << 17) | ((BM / 16) << 24))

template<bool GELU, bool BIAS, bool RES, bool OUT_TF32>
__global__ void __launch_bounds__(256, 1)
tc_gemm(const uint32_t* __restrict__ A, const uint32_t* __restrict__ BT,
        float* __restrict__ C, int M, int N, int K,
        const float* __restrict__ bias, const float* __restrict__ res) {
#if TC_OK
    extern __shared__ char sm_raw[];
    __shared__ uint32_t s_tmem;
    __shared__ __align__(8) uint64_t s_mbar[NSTAGE];

    const int tid = threadIdx.x, wid = tid >> 5, lane = tid & 31;
    const int bm = blockIdx.y * BM, bn = blockIdx.x * BN;

    uint32_t smb_raw = smem_u32(sm_raw);
    uint32_t smb = (smb_raw + 1023u) & ~1023u;
    char* sm = sm_raw + (smb - smb_raw);
    uint32_t mbar0 = smem_u32(&s_mbar[0]);

    if (wid == 4) {
        asm volatile("tcgen05.alloc.cta_group::1.sync.aligned.shared::cta.b32 [%0], %1;"
                     :: "r"(smem_u32(&s_tmem)), "r"(256) : "memory");
    }
    if (tid == 0) { MBAR_INIT(mbar0, 1); MBAR_INIT(mbar0 + 8, 1); MBAR_INIT(mbar0 + 16, 1); }
    __syncthreads();
    const uint32_t tmem = s_tmem;

    const int am = tid >> 3, akq = tid & 7;
    const uint32_t sw0 = SWZ((uint32_t)(am * 128 + akq * 16));
    const int KIT = K / BK;

    // issue all 12 cp.async granules for K-iter j into stage base stb
    #define ISSUE(j, stb) do { \
        const uint32_t* ap = A + (size_t)(bm + am) * K + (j) * BK + akq * 4; \
        _Pragma("unroll") \
        for (int p = 0; p < 4; p++) \
            CPA16(smb + (stb) + p * 4096 + sw0, ap + (size_t)(p * 32) * K); \
        const uint32_t* bp = BT + (size_t)(bn + am) * K + (j) * BK + akq * 4; \
        _Pragma("unroll") \
        for (int p = 0; p < 8; p++) \
            CPA16(smb + (stb) + ABYTES + p * 4096 + sw0, bp + (size_t)(p * 32) * K); \
    } while (0)

    // prologue: fill 3 stages
    #pragma unroll
    for (int j = 0; j < NSTAGE; j++) {
        ISSUE(j, (uint32_t)j * BUFBYTES);
        CPA_COMMIT();
    }

    for (int i = 0; i < KIT; i++) {
        const int s3 = i % NSTAGE;
        const uint32_t stb = (uint32_t)s3 * BUFBYTES;

        CPA_WAIT2();
        __syncthreads();
        asm volatile("fence.proxy.async.shared::cta;" ::: "memory");

        if (wid == 4) {
            uint64_t ad = make_desc_sw128(smb + stb);
            uint64_t bd = make_desc_sw128(smb + stb + ABYTES);
            if (elect1()) {
                #pragma unroll
                for (int kk = 0; kk < 4; kk++) {
                    uint32_t en = (i > 0 || kk > 0) ? 1u : 0u;
                    mma_tf32_ss(tmem, ad + kk * 2, bd + kk * 2, IDESC_TF32, en);
                }
                asm volatile("tcgen05.commit.cta_group::1.mbarrier::arrive::one.shared::cluster.b64 [%0];"
                             :: "r"(mbar0 + 8 * s3) : "memory");
            }
        }

        const int j = i + NSTAGE;
        if (j < KIT) {
            MBAR_WAIT(mbar0 + 8 * s3, (i / NSTAGE) & 1);   // MMA i done reading stage s3
            ISSUE(j, stb);
        }
        CPA_COMMIT();
    }
    #undef ISSUE

    MBAR_WAIT(mbar0 + 8 * ((KIT - 1) % NSTAGE), ((KIT - 1) / NSTAGE) & 1);
    asm volatile("tcgen05.fence::after_thread_sync;" ::: "memory");
    __syncthreads();

    // epilogue: two 128-column halves, staged via padded SMEM
    #pragma unroll
    for (int h = 0; h < 2; h++) {
        if (wid < 4) {
            #pragma unroll
            for (int c = 0; c < 4; c++) {
                uint32_t r[32];
                LDTM_X32(r, tmem + h * 128 + c * 32);
                asm volatile("tcgen05.wait::ld.sync.aligned;" ::: "memory");
                char* row = sm + (wid * 32 + lane) * 528 + c * 128;
                #pragma unroll
                for (int j = 0; j < 8; j++) {
                    float4 v;
                    v.x = __uint_as_float(r[4 * j + 0]);
                    v.y = __uint_as_float(r[4 * j + 1]);
                    v.z = __uint_as_float(r[4 * j + 2]);
                    v.w = __uint_as_float(r[4 * j + 3]);
                    *(float4*)(row + j * 16) = v;
                }
            }
        }
        __syncthreads();
        #pragma unroll
        for (int p = 0; p < 16; p++) {
            int idx = tid + p * 256;
            int r = idx >> 5, cq = idx & 31;
            float4 v = *(float4*)(sm + r * 528 + cq * 16);
            int n = bn + h * 128 + cq * 4;
            size_t off = (size_t)(bm + r) * N + n;
            if (BIAS) {
                float4 bb = *(const float4*)(bias + n);
                v.x += bb.x; v.y += bb.y; v.z += bb.z; v.w += bb.w;
            }
            if (GELU) {
                v.x = 0.5f * v.x * (1.0f + erff(v.x * 0.7071067811865476f));
                v.y = 0.5f * v.y * (1.0f + erff(v.y * 0.7071067811865476f));
                v.z = 0.5f * v.z * (1.0f + erff(v.z * 0.7071067811865476f));
                v.w = 0.5f * v.w * (1.0f + erff(v.w * 0.7071067811865476f));
            }
            if (RES) {
                float4 rr = *(const float4*)(res + off);
                v.x += rr.x; v.y += rr.y; v.z += rr.z; v.w += rr.w;
            }
            if (OUT_TF32) {
                v.x = __uint_as_float(f2tf32(v.x));
                v.y = __uint_as_float(f2tf32(v.y));
                v.z = __uint_as_float(f2tf32(v.z));
                v.w = __uint_as_float(f2tf32(v.w));
            }
            *(float4*)(C + off) = v;
        }
        __syncthreads();
    }

    if (tid == 0) { MBAR_INVAL(mbar0); MBAR_INVAL(mbar0 + 8); MBAR_INVAL(mbar0 + 16); }
    if (wid == 4) {
        asm volatile("tcgen05.dealloc.cta_group::1.sync.aligned.b32 %0, %1;" :: "r"(tmem), "r"(256));
    }
#endif
}

// ---------------- tcgen05 flash attention (causal), QKV packed [M,3072] tf32 ----------------
#define QKVS (3*EMB)
#define ATT_Q 0
#define ATT_K 32768
#define ATT_V 65536
#define ATT_P 98304
#define ATT_SMEM (163840 + 1024)

#define IDESC_S  ((1u << 4) | (2u << 7) | (2u << 10) | (16u << 17) | (8u << 24))
#define IDESC_PV ((1u << 4) | (2u << 7) | (2u << 10) | ( 8u << 17) | (8u << 24))

__global__ void __launch_bounds__(256, 1)
flash_attn_tc(const float* __restrict__ QKV, uint32_t* __restrict__ ctx) {
#if TC_OK
    extern __shared__ char sm_raw[];
    __shared__ uint32_t s_tmem;
    __shared__ __align__(8) uint64_t s_mbar[2];

    const int tid = threadIdx.x, wid = tid >> 5, lane = tid & 31;
    const int qti = gridDim.x - 1 - blockIdx.x;
    const int qt  = qti * 128;
    const int bh  = blockIdx.y;
    const int b   = bh >> 4, h = bh & 15;
    const int base = b * SEQ;
    const int hcol = h * DHEAD;

    uint32_t smb_raw = smem_u32(sm_raw);
    uint32_t smb = (smb_raw + 1023u) & ~1023u;
    char* sm = sm_raw + (smb - smb_raw);
    uint32_t mbar0 = smem_u32(&s_mbar[0]);

    if (wid == 4) {
        asm volatile("tcgen05.alloc.cta_group::1.sync.aligned.shared::cta.b32 [%0], %1;"
                     :: "r"(smem_u32(&s_tmem)), "r"(256) : "memory");
    }
    if (tid == 0) { MBAR_INIT(mbar0, 1); MBAR_INIT(mbar0 + 8, 1); }
    __syncthreads();
    const uint32_t tmem = s_tmem;

    // Q tile: tf32 values * 0.125 (exact power of two -> stays tf32)
    #pragma unroll
    for (int p = 0; p < 8; p++) {
        int idx = tid + p * 256;
        int r = idx >> 4, qd = idx & 15;
        float4 v = *(const float4*)(QKV + (size_t)(base + qt + r) * QKVS + hcol + qd * 4);
        v.x *= 0.125f; v.y *= 0.125f; v.z *= 0.125f; v.w *= 0.125f;
        *(float4*)(sm + ATT_Q + (qd >> 3) * 16384 + SWZ((uint32_t)(r * 128 + (qd & 7) * 16))) = v;
    }

    float m = -INFINITY, sum = 0.f, corr = 0.f;
    float o[64];
    #pragma unroll
    for (int i = 0; i < 64; i++) o[i] = 0.f;
    const int qrow = qt + (wid & 3) * 32 + lane;
    const int ntiles = qti + 1;

    for (int t = 0; t < ntiles; t++) {
        const int k0 = t * 128;
        #pragma unroll
        for (int p = 0; p < 8; p++) {
            int idx = tid + p * 256;
            int r = idx >> 4, qd = idx & 15;
            uint4 v = *(const uint4*)(QKV + (size_t)(base + k0 + r) * QKVS + EMB + hcol + qd * 4);
            *(uint4*)(sm + ATT_K + (qd >> 3) * 16384 + SWZ((uint32_t)(r * 128 + (qd & 7) * 16))) = v;
        }
        #pragma unroll
        for (int p = 0; p < 8; p++) {
            int idx = tid + p * 256;
            int d = idx & 63, kq = idx >> 6;
            const uint32_t* vp = (const uint32_t*)QKV + (size_t)(base + k0 + kq * 4) * QKVS + 2 * EMB + hcol + d;
            uint4 tt;
            tt.x = vp[0];
            tt.y = vp[QKVS];
            tt.z = vp[2 * QKVS];
            tt.w = vp[3 * QKVS];
            *(uint4*)(sm + ATT_V + (kq >> 3) * 8192 + SWZ((uint32_t)(d * 128 + (kq & 7) * 16))) = tt;
        }
        asm volatile("fence.proxy.async.shared::cta;" ::: "memory");
        __syncthreads();

        if (wid == 4 && elect1()) {
            #pragma unroll
            for (int c = 0; c < 2; c++) {
                uint64_t ad = make_desc_sw128(smb + ATT_Q + c * 16384);
                uint64_t bd = make_desc_sw128(smb + ATT_K + c * 16384);
                #pragma unroll
                for (int kk = 0; kk < 4; kk++)
                    mma_tf32_ss(tmem, ad + kk * 2, bd + kk * 2, IDESC_S, (c | kk) ? 1u : 0u);
            }
            asm volatile("tcgen05.commit.cta_group::1.mbarrier::arrive::one.shared::cluster.b64 [%0];"
                         :: "r"(mbar0) : "memory");
        }
        MBAR_WAIT(mbar0, t & 1);

        if (wid < 4) {
            asm volatile("tcgen05.fence::after_thread_sync;" ::: "memory");
            float s[128];
            uint32_t* su = (uint32_t*)s;
            #pragma unroll
            for (int c = 0; c < 4; c++) LDTM_X32(su + 32 * c, tmem + 32 * c);
            asm volatile("tcgen05.wait::ld.sync.aligned;" ::: "memory");

            if (k0 + 127 > qrow) {
                #pragma unroll
                for (int j = 0; j < 128; j++)
                    if (k0 + j > qrow) s[j] = -INFINITY;
            }
            float mn = m;
            #pragma unroll
            for (int j = 0; j < 128; j++) mn = fmaxf(mn, s[j]);
            corr = __expf(m - mn);
            float ls = 0.f;
            #pragma unroll
            for (int j = 0; j < 128; j++) {
                float pv = __expf(s[j] - mn);
                ls += pv;
                su[j] = f2tf32(pv);
            }
            sum = sum * corr + ls;
            m = mn;

            const int r = wid * 32 + lane;
            #pragma unroll
            for (int c = 0; c < 4; c++) {
                #pragma unroll
                for (int jq = 0; jq < 8; jq++) {
                    uint4 tt;
                    tt.x = su[c * 32 + jq * 4 + 0];
                    tt.y = su[c * 32 + jq * 4 + 1];
                    tt.z = su[c * 32 + jq * 4 + 2];
                    tt.w = su[c * 32 + jq * 4 + 3];
                    *(uint4*)(sm + ATT_P + c * 16384 + SWZ((uint32_t)(r * 128 + jq * 16))) = tt;
                }
            }
        }
        asm volatile("fence.proxy.async.shared::cta;" ::: "memory");
        __syncthreads();

        if (wid == 4 && elect1()) {
            #pragma unroll
            for (int c = 0; c < 4; c++) {
                uint64_t ad = make_desc_sw128(smb + ATT_P + c * 16384);
                uint64_t bd = make_desc_sw128(smb + ATT_V + c * 8192);
                #pragma unroll
                for (int kk = 0; kk < 4; kk++)
                    mma_tf32_ss(tmem + 128, ad + kk * 2, bd + kk * 2, IDESC_PV, (c | kk) ? 1u : 0u);
            }
            asm volatile("tcgen05.commit.cta_group::1.mbarrier::arrive::one.shared::cluster.b64 [%0];"
                         :: "r"(mbar0 + 8) : "memory");
        }
        MBAR_WAIT(mbar0 + 8, t & 1);

        if (wid < 4) {
            asm volatile("tcgen05.fence::after_thread_sync;" ::: "memory");
            uint32_t part[64];
            LDTM_X32(part, tmem + 128);
            LDTM_X32(part + 32, tmem + 160);
            asm volatile("tcgen05.wait::ld.sync.aligned;" ::: "memory");
            #pragma unroll
            for (int i = 0; i < 64; i++)
                o[i] = o[i] * corr + __uint_as_float(part[i]);
        }
    }

    if (wid < 4) {
        float inv = 1.0f / sum;
        uint32_t* outp = ctx + (size_t)(base + qrow) * EMB + hcol;
        #pragma unroll
        for (int i = 0; i < 16; i++) {
            uint4 v;
            v.x = f2tf32(o[4 * i + 0] * inv);
            v.y = f2tf32(o[4 * i + 1] * inv);
            v.z = f2tf32(o[4 * i + 2] * inv);
            v.w = f2tf32(o[4 * i + 3] * inv);
            *(uint4*)(outp + 4 * i) = v;
        }
    }

    __syncthreads();
    if (tid == 0) { MBAR_INVAL(mbar0); MBAR_INVAL(mbar0 + 8); }
    if (wid == 4) {
        asm volatile("tcgen05.dealloc.cta_group::1.sync.aligned.b32 %0, %1;" :: "r"(tmem), "r"(256));
    }
#endif
}

// ---------------- launch ----------------
extern "C" void kernel_launch(void* const* d_in, const int* in_sizes, int n_in,
                              void* d_out, int out_size) {
    const float* x     = (const float*)d_in[0];
    const float* Wq    = (const float*)d_in[1];
    const float* Wk    = (const float*)d_in[2];
    const float* Wv    = (const float*)d_in[3];
    const float* Wo    = (const float*)d_in[4];
    const float* bo    = (const float*)d_in[5];
    const float* W1    = (const float*)d_in[6];
    const float* b1    = (const float*)d_in[7];
    const float* W2    = (const float*)d_in[8];
    const float* b2    = (const float*)d_in[9];
    const float* g1    = (const float*)d_in[10];
    const float* beta1 = (const float*)d_in[11];
    const float* g2    = (const float*)d_in[12];
    const float* beta2 = (const float*)d_in[13];
    float* out = (float*)d_out;

    uint32_t *lnx, *qkv, *ctx, *mid, *wqkv_t, *wo_t, *w1_t, *w2_t;
    float *h;
    cudaGetSymbolAddress((void**)&lnx,    g_lnx);
    cudaGetSymbolAddress((void**)&qkv,    g_qkv);
    cudaGetSymbolAddress((void**)&ctx,    g_ctx);
    cudaGetSymbolAddress((void**)&h,      g_h);
    cudaGetSymbolAddress((void**)&mid,    g_mid);
    cudaGetSymbolAddress((void**)&wqkv_t, g_wqkv_t);
    cudaGetSymbolAddress((void**)&wo_t,   g_wo_t);
    cudaGetSymbolAddress((void**)&w1_t,   g_w1_t);
    cudaGetSymbolAddress((void**)&w2_t,   g_w2_t);

    cudaFuncSetAttribute(tc_gemm<false,false,false,true >, cudaFuncAttributeMaxDynamicSharedMemorySize, SMEM_DYN);
    cudaFuncSetAttribute(tc_gemm<false,true, true, false>, cudaFuncAttributeMaxDynamicSharedMemorySize, SMEM_DYN);
    cudaFuncSetAttribute(tc_gemm<true, true, false,true >, cudaFuncAttributeMaxDynamicSharedMemorySize, SMEM_DYN);
    cudaFuncSetAttribute(flash_attn_tc, cudaFuncAttributeMaxDynamicSharedMemorySize, ATT_SMEM);

    dim3 t256(256);
    transpose_cvt_kernel<<<dim3(EMB/32, EMB/32), t256>>>(Wq, wqkv_t,                     EMB, EMB);
    transpose_cvt_kernel<<<dim3(EMB/32, EMB/32), t256>>>(Wk, wqkv_t + (size_t)EMB*EMB,   EMB, EMB);
    transpose_cvt_kernel<<<dim3(EMB/32, EMB/32), t256>>>(Wv, wqkv_t + (size_t)2*EMB*EMB, EMB, EMB);
    transpose_cvt_kernel<<<dim3(EMB/32, EMB/32), t256>>>(Wo, wo_t, EMB, EMB);
    transpose_cvt_kernel<<<dim3(FFN/32, EMB/32), t256>>>(W1, w1_t, EMB, FFN);
    transpose_cvt_kernel<<<dim3(EMB/32, FFN/32), t256>>>(W2, w2_t, FFN, EMB);

    layernorm_kernel<<<MTOT, 256>>>(x, g1, beta1, lnx);
    // fused QKV: [8192, 3072], tf32 out
    tc_gemm<false,false,false,true><<<dim3(3*EMB/BN, MTOT/BM), 256, SMEM_DYN>>>(
        lnx, wqkv_t, (float*)qkv, MTOT, 3*EMB, EMB, nullptr, nullptr);
    flash_attn_tc<<<dim3(SEQ/128, BATCH*HEADS), 256, ATT_SMEM>>>((const float*)qkv, ctx);
    // Wo + bias + residual(x) -> h (fp32)
    tc_gemm<false,true,true,false><<<dim3(EMB/BN, MTOT/BM), 256, SMEM_DYN>>>(
        ctx, wo_t, h, MTOT, EMB, EMB, bo, x);
    layernorm_kernel<<<MTOT, 256>>>(h, g2, beta2, lnx);
    // FFN1 + bias + GELU -> mid (tf32)
    tc_gemm<true,true,false,true><<<dim3(FFN/BN, MTOT/BM), 256, SMEM_DYN>>>(
        lnx, w1_t, (float*)mid, MTOT, FFN, EMB, b1, nullptr);
    // FFN2 + bias + residual(h) -> out (fp32)
    tc_gemm<false,true,true,false><<<dim3(EMB/BN, MTOT/BM), 256, SMEM_DYN>>>(
        mid, w2_t, out, MTOT, EMB, FFN, b2, h);
}

// round 7
// speedup vs baseline: 8.8397x; 1.0227x over previous
#include <cuda_runtime.h>
#include <math.h>
#include <stdint.h>

// Problem constants
#define BATCH 4
#define SEQ   2048
#define EMB   1024
#define HEADS 16
#define DHEAD 64
#define MTOT  (BATCH*SEQ)      // 8192
#define FFN   (4*EMB)          // 4096

#if defined(__CUDA_ARCH__) && (defined(__CUDA_ARCH_FEAT_SM103_ALL) || defined(__CUDA_ARCH_FEAT_SM100_ALL))
#define TC_OK 1
#else
#define TC_OK 0
#endif

// ---------------- scratch (no allocs allowed) ----------------
__device__ uint32_t g_lnx [(size_t)MTOT*EMB];       // tf32
__device__ uint32_t g_qkv [(size_t)MTOT*3*EMB];     // tf32
__device__ uint32_t g_ctx [(size_t)MTOT*EMB];       // tf32
__device__ float    g_h   [(size_t)MTOT*EMB];       // fp32
__device__ uint32_t g_mid [(size_t)MTOT*FFN];       // tf32
__device__ uint32_t g_wqkv_t[(size_t)3*EMB*EMB];    // [3072,1024] tf32
__device__ uint32_t g_wo_t  [(size_t)EMB*EMB];
__device__ uint32_t g_w1_t  [(size_t)FFN*EMB];
__device__ uint32_t g_w2_t  [(size_t)EMB*FFN];

// ---------------- helpers ----------------
__device__ __forceinline__ uint32_t smem_u32(const void* p) {
    uint32_t a;
    asm("{ .reg .u64 t; cvta.to.shared.u64 t, %1; cvt.u32.u64 %0, t; }" : "=r"(a) : "l"(p));
    return a;
}
__device__ __forceinline__ uint32_t f2tf32(float f) {
    uint32_t r;
    asm("cvt.rna.tf32.f32 %0, %1;" : "=r"(r) : "f"(f));
    return r;
}
#define SWZ(o) ((o) ^ (((o) >> 3) & 0x70))

#define MBAR_INIT(a, c) asm volatile("mbarrier.init.shared.b64 [%0], %1;" :: "r"(a), "r"(c) : "memory")
#define MBAR_INVAL(a)   asm volatile("mbarrier.inval.shared.b64 [%0];" :: "r"(a) : "memory")
#define MBAR_WAIT(a, ph) do { \
    uint32_t _m = (a); uint32_t _p = (ph); uint32_t _d; \
    asm volatile("{ .reg .pred p; mbarrier.try_wait.parity.acquire.cta.shared::cta.b64 p, [%1], %2; selp.b32 %0,1,0,p; }" \
        : "=r"(_d) : "r"(_m), "r"(_p) : "memory"); \
    if (!_d) { \
        asm volatile("{ .reg .pred P1; WL_%=: mbarrier.try_wait.parity.acquire.cta.shared::cta.b64 P1, [%0], %1, 0x989680; @P1 bra.uni WD_%=; bra.uni WL_%=; WD_%=: }" \
            :: "r"(_m), "r"(_p) : "memory"); \
    } } while (0)

#define CPA16(dst, src) asm volatile("cp.async.cg.shared.global [%0], [%1], 16;" :: "r"(dst), "l"(src) : "memory")
#define CPA_COMMIT() asm volatile("cp.async.commit_group;" ::: "memory")
#define CPA_WAIT2()  asm volatile("cp.async.wait_group 2;" ::: "memory")

#if TC_OK
__device__ __forceinline__ uint32_t elect1() {
    uint32_t p;
    asm volatile("{ .reg .pred p; elect.sync _|p, 0xFFFFFFFF; selp.b32 %0,1,0,p; }" : "=r"(p));
    return p;
}
__device__ __forceinline__ uint64_t make_desc_sw128(uint32_t addr) {
    const uint64_t base = (2ull << 61) | (1ull << 46) | (64ull << 32) | (1ull << 16);
    return base | ((uint64_t)(addr >> 4) & 0x3FFF);
}
#define LDTM_X32(r, addr) \
    asm volatile("tcgen05.ld.sync.aligned.32x32b.x32.b32 " \
        "{%0,%1,%2,%3,%4,%5,%6,%7,%8,%9,%10,%11,%12,%13,%14,%15," \
        "%16,%17,%18,%19,%20,%21,%22,%23,%24,%25,%26,%27,%28,%29,%30,%31}, [%32];" \
        : "=r"((r)[0]),"=r"((r)[1]),"=r"((r)[2]),"=r"((r)[3]),"=r"((r)[4]),"=r"((r)[5]),"=r"((r)[6]),"=r"((r)[7]), \
          "=r"((r)[8]),"=r"((r)[9]),"=r"((r)[10]),"=r"((r)[11]),"=r"((r)[12]),"=r"((r)[13]),"=r"((r)[14]),"=r"((r)[15]), \
          "=r"((r)[16]),"=r"((r)[17]),"=r"((r)[18]),"=r"((r)[19]),"=r"((r)[20]),"=r"((r)[21]),"=r"((r)[22]),"=r"((r)[23]), \
          "=r"((r)[24]),"=r"((r)[25]),"=r"((r)[26]),"=r"((r)[27]),"=r"((r)[28]),"=r"((r)[29]),"=r"((r)[30]),"=r"((r)[31]) \
        : "r"(addr))

__device__ __forceinline__ void mma_tf32_ss(uint32_t d, uint64_t ad, uint64_t bd,
                                            uint32_t idesc, uint32_t en) {
    asm volatile("{\n\t.reg .pred p;\n\tsetp.ne.u32 p, %5, 0;\n\t"
        "tcgen05.mma.cta_group::1.kind::tf32 [%0], %1, %2, %3, {%4,%4,%4,%4}, p;\n\t}"
        :: "r"(d), "l"(ad), "l"(bd), "r"(idesc), "r"(0u), "r"(en) : "memory");
}
#endif

// ---------------- merged weight prep: 6 transposes in one launch ----------------
// tiles: [0,4096) Wq/Wk/Wv/Wo (each 1024 tiles of 32x32), [4096,8192) W1, [8192,12288) W2
__global__ void prep_weights_kernel(const float* __restrict__ Wq, const float* __restrict__ Wk,
                                    const float* __restrict__ Wv, const float* __restrict__ Wo,
                                    const float* __restrict__ W1, const float* __restrict__ W2,
                                    uint32_t* __restrict__ wqkv_t, uint32_t* __restrict__ wo_t,
                                    uint32_t* __restrict__ w1_t, uint32_t* __restrict__ w2_t) {
    __shared__ float t[32][33];
    int id = blockIdx.x;
    const float* W; uint32_t* WT; int K, N, n0, k0;
    if (id < 4096) {
        int w = id >> 10; id &= 1023;
        K = EMB; N = EMB;
        W  = (w == 0) ? Wq : (w == 1) ? Wk : (w == 2) ? Wv : Wo;
        WT = (w < 3) ? (wqkv_t + (size_t)w * EMB * EMB) : wo_t;
        n0 = (id & 31) * 32; k0 = (id >> 5) * 32;
    } else if (id < 8192) {
        id -= 4096; K = EMB; N = FFN; W = W1; WT = w1_t;
        n0 = (id & 127) * 32; k0 = (id >> 7) * 32;
    } else {
        id -= 8192; K = FFN; N = EMB; W = W2; WT = w2_t;
        n0 = (id & 31) * 32; k0 = (id >> 5) * 32;
    }
    const int tx = threadIdx.x & 31, ty = threadIdx.x >> 5;
    #pragma unroll
    for (int j = 0; j < 32; j += 8)
        t[ty + j][tx] = W[(size_t)(k0 + ty + j) * N + n0 + tx];
    __syncthreads();
    #pragma unroll
    for (int j = 0; j < 32; j += 8)
        WT[(size_t)(n0 + ty + j) * K + k0 + tx] = f2tf32(t[tx][ty + j]);
}

// ---------------- LayerNorm -> tf32 out ----------------
__device__ __forceinline__ float warp_sum(float v) {
    #pragma unroll
    for (int o = 16; o > 0; o >>= 1) v += __shfl_xor_sync(0xffffffffu, v, o);
    return v;
}

__global__ void layernorm_kernel(const float* __restrict__ x,
                                 const float* __restrict__ gamma,
                                 const float* __restrict__ beta,
                                 uint32_t* __restrict__ out) {
    const int row = blockIdx.x;
    const float* xr = x + (size_t)row * EMB;
    float s = 0.f, s2 = 0.f;
    for (int i = threadIdx.x; i < EMB; i += blockDim.x) {
        float v = xr[i];
        s += v; s2 += v * v;
    }
    s = warp_sum(s); s2 = warp_sum(s2);
    __shared__ float sh[2][8];
    int lane = threadIdx.x & 31, wid = threadIdx.x >> 5;
    if (lane == 0) { sh[0][wid] = s; sh[1][wid] = s2; }
    __syncthreads();
    if (wid == 0) {
        float a = (lane < 8) ? sh[0][lane] : 0.f;
        float b = (lane < 8) ? sh[1][lane] : 0.f;
        a = warp_sum(a); b = warp_sum(b);
        if (lane == 0) { sh[0][0] = a; sh[1][0] = b; }
    }
    __syncthreads();
    float mean = sh[0][0] * (1.0f / EMB);
    float var  = sh[1][0] * (1.0f / EMB) - mean * mean;
    float inv  = rsqrtf(var + 1e-5f);
    uint32_t* outr = out + (size_t)row * EMB;
    for (int i = threadIdx.x; i < EMB; i += blockDim.x) {
        outr[i] = f2tf32(gamma[i] * ((xr[i] - mean) * inv) + beta[i]);
    }
}

// ---------------- tcgen05 tf32 GEMM: 256x256 tile (2x 128x256 MMA), BK=32, 3-stage cp.async ----------------
#define BM 256
#define BN 256
#define BK 32
#define ABYTES (BM*128)            // 32768
#define BBYTES (BN*128)            // 32768
#define BUFBYTES (ABYTES+BBYTES)   // 65536
#define NSTAGE 3
#define SMEM_DYN (NSTAGE*BUFBYTES + 1024)   // 197632

#define IDESC_TF32 ((1u << 4) | (2u << 7) | (2u << 10) | ((BN / 8) << 17) | (8u << 24))  // M=128 per MMA

template<bool GELU, bool BIAS, bool RES, bool OUT_TF32>
__global__ void __launch_bounds__(256, 1)
tc_gemm(const uint32_t* __restrict__ A, const uint32_t* __restrict__ BT,
        float* __restrict__ C, int M, int N, int K,
        const float* __restrict__ bias, const float* __restrict__ res) {
#if TC_OK
    extern __shared__ char sm_raw[];
    __shared__ uint32_t s_tmem;
    __shared__ __align__(8) uint64_t s_mbar[NSTAGE];

    const int tid = threadIdx.x, wid = tid >> 5, lane = tid & 31;
    const int bm = blockIdx.y * BM, bn = blockIdx.x * BN;

    uint32_t smb_raw = smem_u32(sm_raw);
    uint32_t smb = (smb_raw + 1023u) & ~1023u;
    char* sm = sm_raw + (smb - smb_raw);
    uint32_t mbar0 = smem_u32(&s_mbar[0]);

    if (wid == 4) {
        asm volatile("tcgen05.alloc.cta_group::1.sync.aligned.shared::cta.b32 [%0], %1;"
                     :: "r"(smem_u32(&s_tmem)), "r"(512) : "memory");
    }
    if (tid == 0) { MBAR_INIT(mbar0, 1); MBAR_INIT(mbar0 + 8, 1); MBAR_INIT(mbar0 + 16, 1); }
    __syncthreads();
    const uint32_t tmem = s_tmem;

    const int am = tid >> 3, akq = tid & 7;
    const uint32_t sw0 = SWZ((uint32_t)(am * 128 + akq * 16));
    const int KIT = K / BK;

    // 16 cp.async granules per thread per K-iter: A rows am+32p (p=0..7), B rows am+32p
    #define ISSUE(j, stb) do { \
        const uint32_t* ap = A + (size_t)(bm + am) * K + (j) * BK + akq * 4; \
        _Pragma("unroll") \
        for (int p = 0; p < 8; p++) \
            CPA16(smb + (stb) + p * 4096 + sw0, ap + (size_t)(p * 32) * K); \
        const uint32_t* bp = BT + (size_t)(bn + am) * K + (j) * BK + akq * 4; \
        _Pragma("unroll") \
        for (int p = 0; p < 8; p++) \
            CPA16(smb + (stb) + ABYTES + p * 4096 + sw0, bp + (size_t)(p * 32) * K); \
    } while (0)

    #pragma unroll
    for (int j = 0; j < NSTAGE; j++) {
        ISSUE(j, (uint32_t)j * BUFBYTES);
        CPA_COMMIT();
    }

    for (int i = 0; i < KIT; i++) {
        const int s3 = i % NSTAGE;
        const uint32_t stb = (uint32_t)s3 * BUFBYTES;

        CPA_WAIT2();
        __syncthreads();
        asm volatile("fence.proxy.async.shared::cta;" ::: "memory");

        if (wid == 4) {
            uint64_t ad0 = make_desc_sw128(smb + stb);
            uint64_t ad1 = make_desc_sw128(smb + stb + 16384);
            uint64_t bd  = make_desc_sw128(smb + stb + ABYTES);
            if (elect1()) {
                #pragma unroll
                for (int kk = 0; kk < 4; kk++) {
                    uint32_t en = (i > 0 || kk > 0) ? 1u : 0u;
                    mma_tf32_ss(tmem, ad0 + kk * 2, bd + kk * 2, IDESC_TF32, en);
                }
                #pragma unroll
                for (int kk = 0; kk < 4; kk++) {
                    uint32_t en = (i > 0 || kk > 0) ? 1u : 0u;
                    mma_tf32_ss(tmem + 256, ad1 + kk * 2, bd + kk * 2, IDESC_TF32, en);
                }
                asm volatile("tcgen05.commit.cta_group::1.mbarrier::arrive::one.shared::cluster.b64 [%0];"
                             :: "r"(mbar0 + 8 * s3) : "memory");
            }
        }

        const int j = i + NSTAGE;
        if (j < KIT) {
            MBAR_WAIT(mbar0 + 8 * s3, (i / NSTAGE) & 1);
            ISSUE(j, stb);
        }
        CPA_COMMIT();
    }
    #undef ISSUE

    MBAR_WAIT(mbar0 + 8 * ((KIT - 1) % NSTAGE), ((KIT - 1) / NSTAGE) & 1);
    asm volatile("tcgen05.fence::after_thread_sync;" ::: "memory");
    __syncthreads();

    // epilogue: 2 M-halves x 2 column-halves, staged via padded SMEM
    #pragma unroll
    for (int mh = 0; mh < 2; mh++) {
        #pragma unroll
        for (int h = 0; h < 2; h++) {
            if (wid < 4) {
                #pragma unroll
                for (int c = 0; c < 4; c++) {
                    uint32_t r[32];
                    LDTM_X32(r, tmem + mh * 256 + h * 128 + c * 32);
                    asm volatile("tcgen05.wait::ld.sync.aligned;" ::: "memory");
                    char* row = sm + (wid * 32 + lane) * 528 + c * 128;
                    #pragma unroll
                    for (int j = 0; j < 8; j++) {
                        float4 v;
                        v.x = __uint_as_float(r[4 * j + 0]);
                        v.y = __uint_as_float(r[4 * j + 1]);
                        v.z = __uint_as_float(r[4 * j + 2]);
                        v.w = __uint_as_float(r[4 * j + 3]);
                        *(float4*)(row + j * 16) = v;
                    }
                }
            }
            __syncthreads();
            #pragma unroll
            for (int p = 0; p < 16; p++) {
                int idx = tid + p * 256;
                int r = idx >> 5, cq = idx & 31;
                float4 v = *(float4*)(sm + r * 528 + cq * 16);
                int n = bn + h * 128 + cq * 4;
                size_t off = (size_t)(bm + mh * 128 + r) * N + n;
                if (BIAS) {
                    float4 bb = *(const float4*)(bias + n);
                    v.x += bb.x; v.y += bb.y; v.z += bb.z; v.w += bb.w;
                }
                if (GELU) {
                    v.x = 0.5f * v.x * (1.0f + erff(v.x * 0.7071067811865476f));
                    v.y = 0.5f * v.y * (1.0f + erff(v.y * 0.7071067811865476f));
                    v.z = 0.5f * v.z * (1.0f + erff(v.z * 0.7071067811865476f));
                    v.w = 0.5f * v.w * (1.0f + erff(v.w * 0.7071067811865476f));
                }
                if (RES) {
                    float4 rr = *(const float4*)(res + off);
                    v.x += rr.x; v.y += rr.y; v.z += rr.z; v.w += rr.w;
                }
                if (OUT_TF32) {
                    v.x = __uint_as_float(f2tf32(v.x));
                    v.y = __uint_as_float(f2tf32(v.y));
                    v.z = __uint_as_float(f2tf32(v.z));
                    v.w = __uint_as_float(f2tf32(v.w));
                }
                *(float4*)(C + off) = v;
            }
            __syncthreads();
        }
    }

    if (tid == 0) { MBAR_INVAL(mbar0); MBAR_INVAL(mbar0 + 8); MBAR_INVAL(mbar0 + 16); }
    if (wid == 4) {
        asm volatile("tcgen05.dealloc.cta_group::1.sync.aligned.b32 %0, %1;" :: "r"(tmem), "r"(512));
    }
#endif
}

// ---------------- tcgen05 flash attention (causal), 8-warp split softmax ----------------
#define QKVS (3*EMB)
#define ATT_Q 0
#define ATT_K 32768
#define ATT_V 65536
#define ATT_P 98304
#define ATT_SMEM (163840 + 1024)

#define IDESC_S  ((1u << 4) | (2u << 7) | (2u << 10) | (16u << 17) | (8u << 24))
#define IDESC_PV ((1u << 4) | (2u << 7) | (2u << 10) | ( 8u << 17) | (8u << 24))

__global__ void __launch_bounds__(256, 1)
flash_attn_tc(const float* __restrict__ QKV, uint32_t* __restrict__ ctx) {
#if TC_OK
    extern __shared__ char sm_raw[];
    __shared__ uint32_t s_tmem;
    __shared__ __align__(8) uint64_t s_mbar[2];
    __shared__ float s_rmax[2][128];
    __shared__ float s_rsum[2][128];

    const int tid = threadIdx.x, wid = tid >> 5, lane = tid & 31;
    const int half = wid >> 2;                  // 0: cols 0-63, 1: cols 64-127
    const int row  = (wid & 3) * 32 + lane;     // query row within tile (TMEM subpartition row)
    const int qti = gridDim.x - 1 - blockIdx.x;
    const int qt  = qti * 128;
    const int bh  = blockIdx.y;
    const int b   = bh >> 4, h = bh & 15;
    const int base = b * SEQ;
    const int hcol = h * DHEAD;

    uint32_t smb_raw = smem_u32(sm_raw);
    uint32_t smb = (smb_raw + 1023u) & ~1023u;
    char* sm = sm_raw + (smb - smb_raw);
    uint32_t mbar0 = smem_u32(&s_mbar[0]);

    if (wid == 4) {
        asm volatile("tcgen05.alloc.cta_group::1.sync.aligned.shared::cta.b32 [%0], %1;"
                     :: "r"(smem_u32(&s_tmem)), "r"(256) : "memory");
    }
    if (tid == 0) { MBAR_INIT(mbar0, 1); MBAR_INIT(mbar0 + 8, 1); }
    __syncthreads();
    const uint32_t tmem = s_tmem;

    // Q tile (tf32 * 0.125 exact)
    #pragma unroll
    for (int p = 0; p < 8; p++) {
        int idx = tid + p * 256;
        int r = idx >> 4, qd = idx & 15;
        float4 v = *(const float4*)(QKV + (size_t)(base + qt + r) * QKVS + hcol + qd * 4);
        v.x *= 0.125f; v.y *= 0.125f; v.z *= 0.125f; v.w *= 0.125f;
        *(float4*)(sm + ATT_Q + (qd >> 3) * 16384 + SWZ((uint32_t)(r * 128 + (qd & 7) * 16))) = v;
    }

    float m = -INFINITY, sum = 0.f, corr = 0.f;
    float o[32];
    #pragma unroll
    for (int i = 0; i < 32; i++) o[i] = 0.f;
    const int qrow = qt + row;
    const int ntiles = qti + 1;

    for (int t = 0; t < ntiles; t++) {
        const int k0 = t * 128;
        #pragma unroll
        for (int p = 0; p < 8; p++) {
            int idx = tid + p * 256;
            int r = idx >> 4, qd = idx & 15;
            uint4 v = *(const uint4*)(QKV + (size_t)(base + k0 + r) * QKVS + EMB + hcol + qd * 4);
            *(uint4*)(sm + ATT_K + (qd >> 3) * 16384 + SWZ((uint32_t)(r * 128 + (qd & 7) * 16))) = v;
        }
        #pragma unroll
        for (int p = 0; p < 8; p++) {
            int idx = tid + p * 256;
            int d = idx & 63, kq = idx >> 6;
            const uint32_t* vp = (const uint32_t*)QKV + (size_t)(base + k0 + kq * 4) * QKVS + 2 * EMB + hcol + d;
            uint4 tt;
            tt.x = vp[0];
            tt.y = vp[QKVS];
            tt.z = vp[2 * QKVS];
            tt.w = vp[3 * QKVS];
            *(uint4*)(sm + ATT_V + (kq >> 3) * 8192 + SWZ((uint32_t)(d * 128 + (kq & 7) * 16))) = tt;
        }
        asm volatile("fence.proxy.async.shared::cta;" ::: "memory");
        __syncthreads();

        if (wid == 4 && elect1()) {
            #pragma unroll
            for (int c = 0; c < 2; c++) {
                uint64_t ad = make_desc_sw128(smb + ATT_Q + c * 16384);
                uint64_t bd = make_desc_sw128(smb + ATT_K + c * 16384);
                #pragma unroll
                for (int kk = 0; kk < 4; kk++)
                    mma_tf32_ss(tmem, ad + kk * 2, bd + kk * 2, IDESC_S, (c | kk) ? 1u : 0u);
            }
            asm volatile("tcgen05.commit.cta_group::1.mbarrier::arrive::one.shared::cluster.b64 [%0];"
                         :: "r"(mbar0) : "memory");
        }
        MBAR_WAIT(mbar0, t & 1);
        asm volatile("tcgen05.fence::after_thread_sync;" ::: "memory");

        // --- 8-warp split softmax: this warp owns 64 cols [half*64, half*64+64) of its 32 rows ---
        float s[64];
        uint32_t* su = (uint32_t*)s;
        LDTM_X32(su,      tmem + half * 64);
        LDTM_X32(su + 32, tmem + half * 64 + 32);
        asm volatile("tcgen05.wait::ld.sync.aligned;" ::: "memory");

        const int kb = k0 + half * 64;
        if (kb + 63 > qrow) {
            #pragma unroll
            for (int j = 0; j < 64; j++)
                if (kb + j > qrow) s[j] = -INFINITY;
        }
        float lmax = -INFINITY;
        #pragma unroll
        for (int j = 0; j < 64; j++) lmax = fmaxf(lmax, s[j]);
        s_rmax[half][row] = lmax;
        __syncthreads();
        float mn = fmaxf(m, fmaxf(lmax, s_rmax[1 - half][row]));
        corr = __expf(m - mn);
        float ls = 0.f;
        #pragma unroll
        for (int j = 0; j < 64; j++) {
            float pv = __expf(s[j] - mn);
            ls += pv;
            su[j] = f2tf32(pv);
        }
        s_rsum[half][row] = ls;
        __syncthreads();
        sum = sum * corr + ls + s_rsum[1 - half][row];
        m = mn;

        // write P: this warp covers key-chunks (half*2) and (half*2+1)
        #pragma unroll
        for (int c = 0; c < 2; c++) {
            const int chunk = half * 2 + c;
            #pragma unroll
            for (int jq = 0; jq < 8; jq++) {
                uint4 tt;
                tt.x = su[c * 32 + jq * 4 + 0];
                tt.y = su[c * 32 + jq * 4 + 1];
                tt.z = su[c * 32 + jq * 4 + 2];
                tt.w = su[c * 32 + jq * 4 + 3];
                *(uint4*)(sm + ATT_P + chunk * 16384 + SWZ((uint32_t)(row * 128 + jq * 16))) = tt;
            }
        }
        asm volatile("fence.proxy.async.shared::cta;" ::: "memory");
        __syncthreads();

        if (wid == 4 && elect1()) {
            #pragma unroll
            for (int c = 0; c < 4; c++) {
                uint64_t ad = make_desc_sw128(smb + ATT_P + c * 16384);
                uint64_t bd = make_desc_sw128(smb + ATT_V + c * 8192);
                #pragma unroll
                for (int kk = 0; kk < 4; kk++)
                    mma_tf32_ss(tmem + 128, ad + kk * 2, bd + kk * 2, IDESC_PV, (c | kk) ? 1u : 0u);
            }
            asm volatile("tcgen05.commit.cta_group::1.mbarrier::arrive::one.shared::cluster.b64 [%0];"
                         :: "r"(mbar0 + 8) : "memory");
        }
        MBAR_WAIT(mbar0 + 8, t & 1);
        asm volatile("tcgen05.fence::after_thread_sync;" ::: "memory");

        // accumulate: this warp owns output dims [half*32, half*32+32)
        uint32_t part[32];
        LDTM_X32(part, tmem + 128 + half * 32);
        asm volatile("tcgen05.wait::ld.sync.aligned;" ::: "memory");
        #pragma unroll
        for (int i = 0; i < 32; i++)
            o[i] = o[i] * corr + __uint_as_float(part[i]);
    }

    {
        float inv = 1.0f / sum;
        uint32_t* outp = ctx + (size_t)(base + qrow) * EMB + hcol + half * 32;
        #pragma unroll
        for (int i = 0; i < 8; i++) {
            uint4 v;
            v.x = f2tf32(o[4 * i + 0] * inv);
            v.y = f2tf32(o[4 * i + 1] * inv);
            v.z = f2tf32(o[4 * i + 2] * inv);
            v.w = f2tf32(o[4 * i + 3] * inv);
            *(uint4*)(outp + 4 * i) = v;
        }
    }

    __syncthreads();
    if (tid == 0) { MBAR_INVAL(mbar0); MBAR_INVAL(mbar0 + 8); }
    if (wid == 4) {
        asm volatile("tcgen05.dealloc.cta_group::1.sync.aligned.b32 %0, %1;" :: "r"(tmem), "r"(256));
    }
#endif
}

// ---------------- launch ----------------
extern "C" void kernel_launch(void* const* d_in, const int* in_sizes, int n_in,
                              void* d_out, int out_size) {
    const float* x     = (const float*)d_in[0];
    const float* Wq    = (const float*)d_in[1];
    const float* Wk    = (const float*)d_in[2];
    const float* Wv    = (const float*)d_in[3];
    const float* Wo    = (const float*)d_in[4];
    const float* bo    = (const float*)d_in[5];
    const float* W1    = (const float*)d_in[6];
    const float* b1    = (const float*)d_in[7];
    const float* W2    = (const float*)d_in[8];
    const float* b2    = (const float*)d_in[9];
    const float* g1    = (const float*)d_in[10];
    const float* beta1 = (const float*)d_in[11];
    const float* g2    = (const float*)d_in[12];
    const float* beta2 = (const float*)d_in[13];
    float* out = (float*)d_out;

    uint32_t *lnx, *qkv, *ctx, *mid, *wqkv_t, *wo_t, *w1_t, *w2_t;
    float *h;
    cudaGetSymbolAddress((void**)&lnx,    g_lnx);
    cudaGetSymbolAddress((void**)&qkv,    g_qkv);
    cudaGetSymbolAddress((void**)&ctx,    g_ctx);
    cudaGetSymbolAddress((void**)&h,      g_h);
    cudaGetSymbolAddress((void**)&mid,    g_mid);
    cudaGetSymbolAddress((void**)&wqkv_t, g_wqkv_t);
    cudaGetSymbolAddress((void**)&wo_t,   g_wo_t);
    cudaGetSymbolAddress((void**)&w1_t,   g_w1_t);
    cudaGetSymbolAddress((void**)&w2_t,   g_w2_t);

    cudaFuncSetAttribute(tc_gemm<false,false,false,true >, cudaFuncAttributeMaxDynamicSharedMemorySize, SMEM_DYN);
    cudaFuncSetAttribute(tc_gemm<false,true, true, false>, cudaFuncAttributeMaxDynamicSharedMemorySize, SMEM_DYN);
    cudaFuncSetAttribute(tc_gemm<true, true, false,true >, cudaFuncAttributeMaxDynamicSharedMemorySize, SMEM_DYN);
    cudaFuncSetAttribute(flash_attn_tc, cudaFuncAttributeMaxDynamicSharedMemorySize, ATT_SMEM);

    prep_weights_kernel<<<12288, 256>>>(Wq, Wk, Wv, Wo, W1, W2, wqkv_t, wo_t, w1_t, w2_t);

    layernorm_kernel<<<MTOT, 256>>>(x, g1, beta1, lnx);
    tc_gemm<false,false,false,true><<<dim3(3*EMB/BN, MTOT/BM), 256, SMEM_DYN>>>(
        lnx, wqkv_t, (float*)qkv, MTOT, 3*EMB, EMB, nullptr, nullptr);
    flash_attn_tc<<<dim3(SEQ/128, BATCH*HEADS), 256, ATT_SMEM>>>((const float*)qkv, ctx);
    tc_gemm<false,true,true,false><<<dim3(EMB/BN, MTOT/BM), 256, SMEM_DYN>>>(
        ctx, wo_t, h, MTOT, EMB, EMB, bo, x);
    layernorm_kernel<<<MTOT, 256>>>(h, g2, beta2, lnx);
    tc_gemm<true,true,false,true><<<dim3(FFN/BN, MTOT/BM), 256, SMEM_DYN>>>(
        lnx, w1_t, (float*)mid, MTOT, FFN, EMB, b1, nullptr);
    tc_gemm<false,true,true,false><<<dim3(EMB/BN, MTOT/BM), 256, SMEM_DYN>>>(
        mid, w2_t, out, MTOT, EMB, FFN, b2, h);
}

// round 8
// speedup vs baseline: 9.2630x; 1.0479x over previous
#include <cuda_runtime.h>
#include <math.h>
#include <stdint.h>

// Problem constants
#define BATCH 4
#define SEQ   2048
#define EMB   1024
#define HEADS 16
#define DHEAD 64
#define MTOT  (BATCH*SEQ)      // 8192
#define FFN   (4*EMB)          // 4096

#if defined(__CUDA_ARCH__) && (defined(__CUDA_ARCH_FEAT_SM103_ALL) || defined(__CUDA_ARCH_FEAT_SM100_ALL))
#define TC_OK 1
#else
#define TC_OK 0
#endif

// ---------------- scratch (no allocs allowed) ----------------
__device__ uint32_t g_lnx [(size_t)MTOT*EMB];       // tf32
__device__ uint32_t g_qkv [(size_t)MTOT*3*EMB];     // tf32
__device__ uint32_t g_ctx [(size_t)MTOT*EMB];       // tf32
__device__ float    g_h   [(size_t)MTOT*EMB];       // fp32
__device__ uint32_t g_mid [(size_t)MTOT*FFN];       // tf32
__device__ uint32_t g_wqkv_t[(size_t)3*EMB*EMB];    // [3072,1024] tf32
__device__ uint32_t g_wo_t  [(size_t)EMB*EMB];
__device__ uint32_t g_w1_t  [(size_t)FFN*EMB];
__device__ uint32_t g_w2_t  [(size_t)EMB*FFN];

// ---------------- helpers ----------------
__device__ __forceinline__ uint32_t smem_u32(const void* p) {
    uint32_t a;
    asm("{ .reg .u64 t; cvta.to.shared.u64 t, %1; cvt.u32.u64 %0, t; }" : "=r"(a) : "l"(p));
    return a;
}
__device__ __forceinline__ uint32_t f2tf32(float f) {
    uint32_t r;
    asm("cvt.rna.tf32.f32 %0, %1;" : "=r"(r) : "f"(f));
    return r;
}
__device__ __forceinline__ float ex2(float x) {
    float r;
    asm("ex2.approx.f32 %0, %1;" : "=f"(r) : "f"(x));
    return r;
}
#define SWZ(o) ((o) ^ (((o) >> 3) & 0x70))

#define MBAR_INIT(a, c) asm volatile("mbarrier.init.shared.b64 [%0], %1;" :: "r"(a), "r"(c) : "memory")
#define MBAR_INVAL(a)   asm volatile("mbarrier.inval.shared.b64 [%0];" :: "r"(a) : "memory")
#define MBAR_WAIT(a, ph) do { \
    uint32_t _m = (a); uint32_t _p = (ph); uint32_t _d; \
    asm volatile("{ .reg .pred p; mbarrier.try_wait.parity.acquire.cta.shared::cta.b64 p, [%1], %2; selp.b32 %0,1,0,p; }" \
        : "=r"(_d) : "r"(_m), "r"(_p) : "memory"); \
    if (!_d) { \
        asm volatile("{ .reg .pred P1; WL_%=: mbarrier.try_wait.parity.acquire.cta.shared::cta.b64 P1, [%0], %1, 0x989680; @P1 bra.uni WD_%=; bra.uni WL_%=; WD_%=: }" \
            :: "r"(_m), "r"(_p) : "memory"); \
    } } while (0)

#define CPA16(dst, src) asm volatile("cp.async.cg.shared.global [%0], [%1], 16;" :: "r"(dst), "l"(src) : "memory")
#define CPA_COMMIT() asm volatile("cp.async.commit_group;" ::: "memory")
#define CPA_WAIT2()  asm volatile("cp.async.wait_group 2;" ::: "memory")
#define CPA_WAIT0()  asm volatile("cp.async.wait_group 0;" ::: "memory")

#if TC_OK
__device__ __forceinline__ uint32_t elect1() {
    uint32_t p;
    asm volatile("{ .reg .pred p; elect.sync _|p, 0xFFFFFFFF; selp.b32 %0,1,0,p; }" : "=r"(p));
    return p;
}
__device__ __forceinline__ uint64_t make_desc_sw128(uint32_t addr) {
    const uint64_t base = (2ull << 61) | (1ull << 46) | (64ull << 32) | (1ull << 16);
    return base | ((uint64_t)(addr >> 4) & 0x3FFF);
}
#define LDTM_X32(r, addr) \
    asm volatile("tcgen05.ld.sync.aligned.32x32b.x32.b32 " \
        "{%0,%1,%2,%3,%4,%5,%6,%7,%8,%9,%10,%11,%12,%13,%14,%15," \
        "%16,%17,%18,%19,%20,%21,%22,%23,%24,%25,%26,%27,%28,%29,%30,%31}, [%32];" \
        : "=r"((r)[0]),"=r"((r)[1]),"=r"((r)[2]),"=r"((r)[3]),"=r"((r)[4]),"=r"((r)[5]),"=r"((r)[6]),"=r"((r)[7]), \
          "=r"((r)[8]),"=r"((r)[9]),"=r"((r)[10]),"=r"((r)[11]),"=r"((r)[12]),"=r"((r)[13]),"=r"((r)[14]),"=r"((r)[15]), \
          "=r"((r)[16]),"=r"((r)[17]),"=r"((r)[18]),"=r"((r)[19]),"=r"((r)[20]),"=r"((r)[21]),"=r"((r)[22]),"=r"((r)[23]), \
          "=r"((r)[24]),"=r"((r)[25]),"=r"((r)[26]),"=r"((r)[27]),"=r"((r)[28]),"=r"((r)[29]),"=r"((r)[30]),"=r"((r)[31]) \
        : "r"(addr))

__device__ __forceinline__ void mma_tf32_ss(uint32_t d, uint64_t ad, uint64_t bd,
                                            uint32_t idesc, uint32_t en) {
    asm volatile("{\n\t.reg .pred p;\n\tsetp.ne.u32 p, %5, 0;\n\t"
        "tcgen05.mma.cta_group::1.kind::tf32 [%0], %1, %2, %3, {%4,%4,%4,%4}, p;\n\t}"
        :: "r"(d), "l"(ad), "l"(bd), "r"(idesc), "r"(0u), "r"(en) : "memory");
}
#endif

// ---------------- merged weight prep ----------------
__global__ void prep_weights_kernel(const float* __restrict__ Wq, const float* __restrict__ Wk,
                                    const float* __restrict__ Wv, const float* __restrict__ Wo,
                                    const float* __restrict__ W1, const float* __restrict__ W2,
                                    uint32_t* __restrict__ wqkv_t, uint32_t* __restrict__ wo_t,
                                    uint32_t* __restrict__ w1_t, uint32_t* __restrict__ w2_t) {
    __shared__ float t[32][33];
    int id = blockIdx.x;
    const float* W; uint32_t* WT; int K, N, n0, k0;
    if (id < 4096) {
        int w = id >> 10; id &= 1023;
        K = EMB; N = EMB;
        W  = (w == 0) ? Wq : (w == 1) ? Wk : (w == 2) ? Wv : Wo;
        WT = (w < 3) ? (wqkv_t + (size_t)w * EMB * EMB) : wo_t;
        n0 = (id & 31) * 32; k0 = (id >> 5) * 32;
    } else if (id < 8192) {
        id -= 4096; K = EMB; N = FFN; W = W1; WT = w1_t;
        n0 = (id & 127) * 32; k0 = (id >> 7) * 32;
    } else {
        id -= 8192; K = FFN; N = EMB; W = W2; WT = w2_t;
        n0 = (id & 31) * 32; k0 = (id >> 5) * 32;
    }
    const int tx = threadIdx.x & 31, ty = threadIdx.x >> 5;
    #pragma unroll
    for (int j = 0; j < 32; j += 8)
        t[ty + j][tx] = W[(size_t)(k0 + ty + j) * N + n0 + tx];
    __syncthreads();
    #pragma unroll
    for (int j = 0; j < 32; j += 8)
        WT[(size_t)(n0 + ty + j) * K + k0 + tx] = f2tf32(t[tx][ty + j]);
}

// ---------------- LayerNorm -> tf32 out ----------------
__device__ __forceinline__ float warp_sum(float v) {
    #pragma unroll
    for (int o = 16; o > 0; o >>= 1) v += __shfl_xor_sync(0xffffffffu, v, o);
    return v;
}

__global__ void layernorm_kernel(const float* __restrict__ x,
                                 const float* __restrict__ gamma,
                                 const float* __restrict__ beta,
                                 uint32_t* __restrict__ out) {
    const int row = blockIdx.x;
    const float* xr = x + (size_t)row * EMB;
    float s = 0.f, s2 = 0.f;
    for (int i = threadIdx.x; i < EMB; i += blockDim.x) {
        float v = xr[i];
        s += v; s2 += v * v;
    }
    s = warp_sum(s); s2 = warp_sum(s2);
    __shared__ float sh[2][8];
    int lane = threadIdx.x & 31, wid = threadIdx.x >> 5;
    if (lane == 0) { sh[0][wid] = s; sh[1][wid] = s2; }
    __syncthreads();
    if (wid == 0) {
        float a = (lane < 8) ? sh[0][lane] : 0.f;
        float b = (lane < 8) ? sh[1][lane] : 0.f;
        a = warp_sum(a); b = warp_sum(b);
        if (lane == 0) { sh[0][0] = a; sh[1][0] = b; }
    }
    __syncthreads();
    float mean = sh[0][0] * (1.0f / EMB);
    float var  = sh[1][0] * (1.0f / EMB) - mean * mean;
    float inv  = rsqrtf(var + 1e-5f);
    uint32_t* outr = out + (size_t)row * EMB;
    for (int i = threadIdx.x; i < EMB; i += blockDim.x) {
        outr[i] = f2tf32(gamma[i] * ((xr[i] - mean) * inv) + beta[i]);
    }
}

// ---------------- tcgen05 tf32 GEMM: 256x256 tile, BK=32, 3-stage cp.async ----------------
#define BM 256
#define BN 256
#define BK 32
#define ABYTES (BM*128)
#define BBYTES (BN*128)
#define BUFBYTES (ABYTES+BBYTES)
#define NSTAGE 3
#define SMEM_DYN (NSTAGE*BUFBYTES + 1024)

#define IDESC_TF32 ((1u << 4) | (2u << 7) | (2u << 10) | ((BN / 8) << 17) | (8u << 24))

template<bool GELU, bool BIAS, bool RES, bool OUT_TF32>
__global__ void __launch_bounds__(256, 1)
tc_gemm(const uint32_t* __restrict__ A, const uint32_t* __restrict__ BT,
        float* __restrict__ C, int M, int N, int K,
        const float* __restrict__ bias, const float* __restrict__ res) {
#if TC_OK
    extern __shared__ char sm_raw[];
    __shared__ uint32_t s_tmem;
    __shared__ __align__(8) uint64_t s_mbar[NSTAGE];

    const int tid = threadIdx.x, wid = tid >> 5, lane = tid & 31;
    const int bm = blockIdx.y * BM, bn = blockIdx.x * BN;

    uint32_t smb_raw = smem_u32(sm_raw);
    uint32_t smb = (smb_raw + 1023u) & ~1023u;
    char* sm = sm_raw + (smb - smb_raw);
    uint32_t mbar0 = smem_u32(&s_mbar[0]);

    if (wid == 4) {
        asm volatile("tcgen05.alloc.cta_group::1.sync.aligned.shared::cta.b32 [%0], %1;"
                     :: "r"(smem_u32(&s_tmem)), "r"(512) : "memory");
    }
    if (tid == 0) { MBAR_INIT(mbar0, 1); MBAR_INIT(mbar0 + 8, 1); MBAR_INIT(mbar0 + 16, 1); }
    __syncthreads();
    const uint32_t tmem = s_tmem;

    const int am = tid >> 3, akq = tid & 7;
    const uint32_t sw0 = SWZ((uint32_t)(am * 128 + akq * 16));
    const int KIT = K / BK;

    #define ISSUE(j, stb) do { \
        const uint32_t* ap = A + (size_t)(bm + am) * K + (j) * BK + akq * 4; \
        _Pragma("unroll") \
        for (int p = 0; p < 8; p++) \
            CPA16(smb + (stb) + p * 4096 + sw0, ap + (size_t)(p * 32) * K); \
        const uint32_t* bp = BT + (size_t)(bn + am) * K + (j) * BK + akq * 4; \
        _Pragma("unroll") \
        for (int p = 0; p < 8; p++) \
            CPA16(smb + (stb) + ABYTES + p * 4096 + sw0, bp + (size_t)(p * 32) * K); \
    } while (0)

    #pragma unroll
    for (int j = 0; j < NSTAGE; j++) {
        ISSUE(j, (uint32_t)j * BUFBYTES);
        CPA_COMMIT();
    }

    for (int i = 0; i < KIT; i++) {
        const int s3 = i % NSTAGE;
        const uint32_t stb = (uint32_t)s3 * BUFBYTES;

        CPA_WAIT2();
        __syncthreads();
        asm volatile("fence.proxy.async.shared::cta;" ::: "memory");

        if (wid == 4) {
            uint64_t ad0 = make_desc_sw128(smb + stb);
            uint64_t ad1 = make_desc_sw128(smb + stb + 16384);
            uint64_t bd  = make_desc_sw128(smb + stb + ABYTES);
            if (elect1()) {
                #pragma unroll
                for (int kk = 0; kk < 4; kk++) {
                    uint32_t en = (i > 0 || kk > 0) ? 1u : 0u;
                    mma_tf32_ss(tmem, ad0 + kk * 2, bd + kk * 2, IDESC_TF32, en);
                }
                #pragma unroll
                for (int kk = 0; kk < 4; kk++) {
                    uint32_t en = (i > 0 || kk > 0) ? 1u : 0u;
                    mma_tf32_ss(tmem + 256, ad1 + kk * 2, bd + kk * 2, IDESC_TF32, en);
                }
                asm volatile("tcgen05.commit.cta_group::1.mbarrier::arrive::one.shared::cluster.b64 [%0];"
                             :: "r"(mbar0 + 8 * s3) : "memory");
            }
        }

        const int j = i + NSTAGE;
        if (j < KIT) {
            MBAR_WAIT(mbar0 + 8 * s3, (i / NSTAGE) & 1);
            ISSUE(j, stb);
        }
        CPA_COMMIT();
    }
    #undef ISSUE

    MBAR_WAIT(mbar0 + 8 * ((KIT - 1) % NSTAGE), ((KIT - 1) / NSTAGE) & 1);
    asm volatile("tcgen05.fence::after_thread_sync;" ::: "memory");
    __syncthreads();

    #pragma unroll
    for (int mh = 0; mh < 2; mh++) {
        #pragma unroll
        for (int h = 0; h < 2; h++) {
            if (wid < 4) {
                #pragma unroll
                for (int c = 0; c < 4; c++) {
                    uint32_t r[32];
                    LDTM_X32(r, tmem + mh * 256 + h * 128 + c * 32);
                    asm volatile("tcgen05.wait::ld.sync.aligned;" ::: "memory");
                    char* row = sm + (wid * 32 + lane) * 528 + c * 128;
                    #pragma unroll
                    for (int j = 0; j < 8; j++) {
                        float4 v;
                        v.x = __uint_as_float(r[4 * j + 0]);
                        v.y = __uint_as_float(r[4 * j + 1]);
                        v.z = __uint_as_float(r[4 * j + 2]);
                        v.w = __uint_as_float(r[4 * j + 3]);
                        *(float4*)(row + j * 16) = v;
                    }
                }
            }
            __syncthreads();
            #pragma unroll
            for (int p = 0; p < 16; p++) {
                int idx = tid + p * 256;
                int r = idx >> 5, cq = idx & 31;
                float4 v = *(float4*)(sm + r * 528 + cq * 16);
                int n = bn + h * 128 + cq * 4;
                size_t off = (size_t)(bm + mh * 128 + r) * N + n;
                if (BIAS) {
                    float4 bb = *(const float4*)(bias + n);
                    v.x += bb.x; v.y += bb.y; v.z += bb.z; v.w += bb.w;
                }
                if (GELU) {
                    v.x = 0.5f * v.x * (1.0f + erff(v.x * 0.7071067811865476f));
                    v.y = 0.5f * v.y * (1.0f + erff(v.y * 0.7071067811865476f));
                    v.z = 0.5f * v.z * (1.0f + erff(v.z * 0.7071067811865476f));
                    v.w = 0.5f * v.w * (1.0f + erff(v.w * 0.7071067811865476f));
                }
                if (RES) {
                    float4 rr = *(const float4*)(res + off);
                    v.x += rr.x; v.y += rr.y; v.z += rr.z; v.w += rr.w;
                }
                if (OUT_TF32) {
                    v.x = __uint_as_float(f2tf32(v.x));
                    v.y = __uint_as_float(f2tf32(v.y));
                    v.z = __uint_as_float(f2tf32(v.z));
                    v.w = __uint_as_float(f2tf32(v.w));
                }
                *(float4*)(C + off) = v;
            }
            __syncthreads();
        }
    }

    if (tid == 0) { MBAR_INVAL(mbar0); MBAR_INVAL(mbar0 + 8); MBAR_INVAL(mbar0 + 16); }
    if (wid == 4) {
        asm volatile("tcgen05.dealloc.cta_group::1.sync.aligned.b32 %0, %1;" :: "r"(tmem), "r"(512));
    }
#endif
}

// ---------------- tcgen05 flash attention (causal), pipelined K/V prefetch ----------------
// smem: Q 32K | K buf0 32K | K buf1 32K | V 32K | P 64K
#define QKVS (3*EMB)
#define ATT_Q  0
#define ATT_K0 32768
#define ATT_V  98304
#define ATT_P  131072
#define ATT_SMEM (196608 + 1024)
#define LOG2E 1.4426950408889634f

#define IDESC_S  ((1u << 4) | (2u << 7) | (2u << 10) | (16u << 17) | (8u << 24))
#define IDESC_PV ((1u << 4) | (2u << 7) | (2u << 10) | ( 8u << 17) | (8u << 24))

__global__ void __launch_bounds__(256, 1)
flash_attn_tc(const float* __restrict__ QKV, uint32_t* __restrict__ ctx) {
#if TC_OK
    extern __shared__ char sm_raw[];
    __shared__ uint32_t s_tmem;
    __shared__ __align__(8) uint64_t s_mbar[2];
    __shared__ float s_rmax[2][128];
    __shared__ float s_rsum[2][128];

    const int tid = threadIdx.x, wid = tid >> 5, lane = tid & 31;
    const int half = wid >> 2;
    const int row  = (wid & 3) * 32 + lane;
    const int qti = gridDim.x - 1 - blockIdx.x;
    const int qt  = qti * 128;
    const int bh  = blockIdx.y;
    const int b   = bh >> 4, h = bh & 15;
    const int base = b * SEQ;
    const int hcol = h * DHEAD;

    uint32_t smb_raw = smem_u32(sm_raw);
    uint32_t smb = (smb_raw + 1023u) & ~1023u;
    char* sm = sm_raw + (smb - smb_raw);
    uint32_t mbar0 = smem_u32(&s_mbar[0]);

    if (wid == 4) {
        asm volatile("tcgen05.alloc.cta_group::1.sync.aligned.shared::cta.b32 [%0], %1;"
                     :: "r"(smem_u32(&s_tmem)), "r"(256) : "memory");
    }
    if (tid == 0) { MBAR_INIT(mbar0, 1); MBAR_INIT(mbar0 + 8, 1); }
    __syncthreads();
    const uint32_t tmem = s_tmem;

    // per-thread K-load coords (also used for Q)
    const int kr = tid >> 4, kqd = tid & 15;   // with p: idx = tid + p*256 -> r = kr + 16p

    // prologue: Q load (scaled into log2 domain), K(0) cp.async, V(0) LDG prefetch
    #pragma unroll
    for (int p = 0; p < 8; p++) {
        int r = kr + p * 16;
        float4 v = *(const float4*)(QKV + (size_t)(base + qt + r) * QKVS + hcol + kqd * 4);
        uint4 t;
        t.x = f2tf32(v.x * (0.125f * LOG2E));
        t.y = f2tf32(v.y * (0.125f * LOG2E));
        t.z = f2tf32(v.z * (0.125f * LOG2E));
        t.w = f2tf32(v.w * (0.125f * LOG2E));
        *(uint4*)(sm + ATT_Q + (kqd >> 3) * 16384 + SWZ((uint32_t)(r * 128 + (kqd & 7) * 16))) = t;
    }
    #pragma unroll
    for (int p = 0; p < 8; p++) {
        int r = kr + p * 16;
        CPA16(smb + ATT_K0 + (kqd >> 3) * 16384 + SWZ((uint32_t)(r * 128 + (kqd & 7) * 16)),
              QKV + (size_t)(base + r) * QKVS + EMB + hcol + kqd * 4);
    }
    CPA_COMMIT();

    const int vd = tid & 63, vkq = tid >> 6;   // with p: kq = vkq + 4p
    uint4 rv[8];
    #pragma unroll
    for (int p = 0; p < 8; p++) {
        int kq = vkq + p * 4;
        const uint32_t* vp = (const uint32_t*)QKV + (size_t)(base + kq * 4) * QKVS + 2 * EMB + hcol + vd;
        rv[p].x = vp[0];
        rv[p].y = vp[QKVS];
        rv[p].z = vp[2 * QKVS];
        rv[p].w = vp[3 * QKVS];
    }

    float m = -INFINITY, sum = 0.f, corr = 0.f;
    float o[32];
    #pragma unroll
    for (int i = 0; i < 32; i++) o[i] = 0.f;
    const int qrow = qt + row;
    const int ntiles = qti + 1;

    for (int t = 0; t < ntiles; t++) {
        const int k0 = t * 128;
        const uint32_t kbuf = ATT_K0 + (uint32_t)(t & 1) * 32768;

        // V(t): regs -> smem (V buffer free: PV(t-1) completed)
        #pragma unroll
        for (int p = 0; p < 8; p++) {
            int kq = vkq + p * 4;
            *(uint4*)(sm + ATT_V + (kq >> 3) * 8192 + SWZ((uint32_t)(vd * 128 + (kq & 7) * 16))) = rv[p];
        }

        CPA_WAIT0();                       // K(t) landed
        asm volatile("fence.proxy.async.shared::cta;" ::: "memory");
        __syncthreads();

        // S = Q @ K^T
        if (wid == 4 && elect1()) {
            #pragma unroll
            for (int c = 0; c < 2; c++) {
                uint64_t ad = make_desc_sw128(smb + ATT_Q + c * 16384);
                uint64_t bd = make_desc_sw128(smb + kbuf + c * 16384);
                #pragma unroll
                for (int kk = 0; kk < 4; kk++)
                    mma_tf32_ss(tmem, ad + kk * 2, bd + kk * 2, IDESC_S, (c | kk) ? 1u : 0u);
            }
            asm volatile("tcgen05.commit.cta_group::1.mbarrier::arrive::one.shared::cluster.b64 [%0];"
                         :: "r"(mbar0) : "memory");
        }

        // prefetch K(t+1) cp.async + V(t+1) LDG (overlap S-MMA + softmax + PV)
        if (t + 1 < ntiles) {
            const int nk0 = k0 + 128;
            const uint32_t nkbuf = ATT_K0 + (uint32_t)((t + 1) & 1) * 32768;
            #pragma unroll
            for (int p = 0; p < 8; p++) {
                int r = kr + p * 16;
                CPA16(smb + nkbuf + (kqd >> 3) * 16384 + SWZ((uint32_t)(r * 128 + (kqd & 7) * 16)),
                      QKV + (size_t)(base + nk0 + r) * QKVS + EMB + hcol + kqd * 4);
            }
            #pragma unroll
            for (int p = 0; p < 8; p++) {
                int kq = vkq + p * 4;
                const uint32_t* vp = (const uint32_t*)QKV + (size_t)(base + nk0 + kq * 4) * QKVS + 2 * EMB + hcol + vd;
                rv[p].x = vp[0];
                rv[p].y = vp[QKVS];
                rv[p].z = vp[2 * QKVS];
                rv[p].w = vp[3 * QKVS];
            }
        }
        CPA_COMMIT();

        MBAR_WAIT(mbar0, t & 1);
        asm volatile("tcgen05.fence::after_thread_sync;" ::: "memory");

        // split softmax: warp owns 64 cols [half*64, half*64+64) of its 32 rows (log2 domain)
        float s[64];
        uint32_t* su = (uint32_t*)s;
        LDTM_X32(su,      tmem + half * 64);
        LDTM_X32(su + 32, tmem + half * 64 + 32);
        asm volatile("tcgen05.wait::ld.sync.aligned;" ::: "memory");

        const int kb = k0 + half * 64;
        if (kb + 63 > qrow) {
            #pragma unroll
            for (int j = 0; j < 64; j++)
                if (kb + j > qrow) s[j] = -INFINITY;
        }
        float lmax = -INFINITY;
        #pragma unroll
        for (int j = 0; j < 64; j++) lmax = fmaxf(lmax, s[j]);
        s_rmax[half][row] = lmax;
        __syncthreads();
        float mn = fmaxf(m, fmaxf(lmax, s_rmax[1 - half][row]));
        corr = ex2(m - mn);
        float ls = 0.f;
        #pragma unroll
        for (int j = 0; j < 64; j++) {
            float pv = ex2(s[j] - mn);
            ls += pv;
            su[j] = f2tf32(pv);
        }
        s_rsum[half][row] = ls;
        __syncthreads();
        sum = sum * corr + ls + s_rsum[1 - half][row];
        m = mn;

        #pragma unroll
        for (int c = 0; c < 2; c++) {
            const int chunk = half * 2 + c;
            #pragma unroll
            for (int jq = 0; jq < 8; jq++) {
                uint4 tt;
                tt.x = su[c * 32 + jq * 4 + 0];
                tt.y = su[c * 32 + jq * 4 + 1];
                tt.z = su[c * 32 + jq * 4 + 2];
                tt.w = su[c * 32 + jq * 4 + 3];
                *(uint4*)(sm + ATT_P + chunk * 16384 + SWZ((uint32_t)(row * 128 + jq * 16))) = tt;
            }
        }
        asm volatile("fence.proxy.async.shared::cta;" ::: "memory");
        __syncthreads();

        if (wid == 4 && elect1()) {
            #pragma unroll
            for (int c = 0; c < 4; c++) {
                uint64_t ad = make_desc_sw128(smb + ATT_P + c * 16384);
                uint64_t bd = make_desc_sw128(smb + ATT_V + c * 8192);
                #pragma unroll
                for (int kk = 0; kk < 4; kk++)
                    mma_tf32_ss(tmem + 128, ad + kk * 2, bd + kk * 2, IDESC_PV, (c | kk) ? 1u : 0u);
            }
            asm volatile("tcgen05.commit.cta_group::1.mbarrier::arrive::one.shared::cluster.b64 [%0];"
                         :: "r"(mbar0 + 8) : "memory");
        }
        MBAR_WAIT(mbar0 + 8, t & 1);
        asm volatile("tcgen05.fence::after_thread_sync;" ::: "memory");

        uint32_t part[32];
        LDTM_X32(part, tmem + 128 + half * 32);
        asm volatile("tcgen05.wait::ld.sync.aligned;" ::: "memory");
        #pragma unroll
        for (int i = 0; i < 32; i++)
            o[i] = o[i] * corr + __uint_as_float(part[i]);
    }

    {
        float inv = 1.0f / sum;
        uint32_t* outp = ctx + (size_t)(base + qrow) * EMB + hcol + half * 32;
        #pragma unroll
        for (int i = 0; i < 8; i++) {
            uint4 v;
            v.x = f2tf32(o[4 * i + 0] * inv);
            v.y = f2tf32(o[4 * i + 1] * inv);
            v.z = f2tf32(o[4 * i + 2] * inv);
            v.w = f2tf32(o[4 * i + 3] * inv);
            *(uint4*)(outp + 4 * i) = v;
        }
    }

    __syncthreads();
    if (tid == 0) { MBAR_INVAL(mbar0); MBAR_INVAL(mbar0 + 8); }
    if (wid == 4) {
        asm volatile("tcgen05.dealloc.cta_group::1.sync.aligned.b32 %0, %1;" :: "r"(tmem), "r"(256));
    }
#endif
}

// ---------------- launch ----------------
extern "C" void kernel_launch(void* const* d_in, const int* in_sizes, int n_in,
                              void* d_out, int out_size) {
    const float* x     = (const float*)d_in[0];
    const float* Wq    = (const float*)d_in[1];
    const float* Wk    = (const float*)d_in[2];
    const float* Wv    = (const float*)d_in[3];
    const float* Wo    = (const float*)d_in[4];
    const float* bo    = (const float*)d_in[5];
    const float* W1    = (const float*)d_in[6];
    const float* b1    = (const float*)d_in[7];
    const float* W2    = (const float*)d_in[8];
    const float* b2    = (const float*)d_in[9];
    const float* g1    = (const float*)d_in[10];
    const float* beta1 = (const float*)d_in[11];
    const float* g2    = (const float*)d_in[12];
    const float* beta2 = (const float*)d_in[13];
    float* out = (float*)d_out;

    uint32_t *lnx, *qkv, *ctx, *mid, *wqkv_t, *wo_t, *w1_t, *w2_t;
    float *h;
    cudaGetSymbolAddress((void**)&lnx,    g_lnx);
    cudaGetSymbolAddress((void**)&qkv,    g_qkv);
    cudaGetSymbolAddress((void**)&ctx,    g_ctx);
    cudaGetSymbolAddress((void**)&h,      g_h);
    cudaGetSymbolAddress((void**)&mid,    g_mid);
    cudaGetSymbolAddress((void**)&wqkv_t, g_wqkv_t);
    cudaGetSymbolAddress((void**)&wo_t,   g_wo_t);
    cudaGetSymbolAddress((void**)&w1_t,   g_w1_t);
    cudaGetSymbolAddress((void**)&w2_t,   g_w2_t);

    cudaFuncSetAttribute(tc_gemm<false,false,false,true >, cudaFuncAttributeMaxDynamicSharedMemorySize, SMEM_DYN);
    cudaFuncSetAttribute(tc_gemm<false,true, true, false>, cudaFuncAttributeMaxDynamicSharedMemorySize, SMEM_DYN);
    cudaFuncSetAttribute(tc_gemm<true, true, false,true >, cudaFuncAttributeMaxDynamicSharedMemorySize, SMEM_DYN);
    cudaFuncSetAttribute(flash_attn_tc, cudaFuncAttributeMaxDynamicSharedMemorySize, ATT_SMEM);

    prep_weights_kernel<<<12288, 256>>>(Wq, Wk, Wv, Wo, W1, W2, wqkv_t, wo_t, w1_t, w2_t);

    layernorm_kernel<<<MTOT, 256>>>(x, g1, beta1, lnx);
    tc_gemm<false,false,false,true><<<dim3(3*EMB/BN, MTOT/BM), 256, SMEM_DYN>>>(
        lnx, wqkv_t, (float*)qkv, MTOT, 3*EMB, EMB, nullptr, nullptr);
    flash_attn_tc<<<dim3(SEQ/128, BATCH*HEADS), 256, ATT_SMEM>>>((const float*)qkv, ctx);
    tc_gemm<false,true,true,false><<<dim3(EMB/BN, MTOT/BM), 256, SMEM_DYN>>>(
        ctx, wo_t, h, MTOT, EMB, EMB, bo, x);
    layernorm_kernel<<<MTOT, 256>>>(h, g2, beta2, lnx);
    tc_gemm<true,true,false,true><<<dim3(FFN/BN, MTOT/BM), 256, SMEM_DYN>>>(
        lnx, w1_t, (float*)mid, MTOT, FFN, EMB, b1, nullptr);
    tc_gemm<false,true,true,false><<<dim3(EMB/BN, MTOT/BM), 256, SMEM_DYN>>>(
        mid, w2_t, out, MTOT, EMB, FFN, b2, h);
}